// round 1
// baseline (speedup 1.0000x reference)
#include <cuda_runtime.h>

// Problem constants
static constexpr int BATCH = 4;
static constexpr int SEQ   = 2048;
static constexpr int DM    = 1024;
static constexpr int NH    = 16;
static constexpr int DH    = 64;      // head dim
static constexpr int ROWS  = BATCH * SEQ;   // 8192

// Scratch (device globals: allocation-free)
__device__ float g_Q[(size_t)ROWS * DM];
__device__ float g_K[(size_t)ROWS * DM];
__device__ float g_V[(size_t)ROWS * DM];
__device__ float g_T[(size_t)ROWS * DM];

// ---------------------------------------------------------------------------
// SGEMM NT: C[M,N] = A[M,K] @ B[N,K]^T   (all row-major, M%128==0, N%128==0, K%32==0)
// 128x128 block tile, BK=32, 256 threads, 8x8 per thread.
// ---------------------------------------------------------------------------
__global__ __launch_bounds__(256) void sgemm_nt_kernel(
    const float* __restrict__ A, const float* __restrict__ B,
    float* __restrict__ C, int M, int N, int K)
{
    constexpr int BM = 128, BN = 128, BK = 32;
    __shared__ float As[BK * BM];   // transposed: As[k][m]
    __shared__ float Bs[BK * BN];   // transposed: Bs[k][n]

    const int tid = threadIdx.x;
    const int tx  = tid & 15;       // 0..15
    const int ty  = tid >> 4;       // 0..15
    const int row0 = blockIdx.y * BM;
    const int col0 = blockIdx.x * BN;

    float acc[8][8];
    #pragma unroll
    for (int i = 0; i < 8; i++)
        #pragma unroll
        for (int j = 0; j < 8; j++) acc[i][j] = 0.0f;

    for (int k0 = 0; k0 < K; k0 += BK) {
        // Load 128x32 tiles of A and B (1024 float4 each; 4 per thread), store transposed.
        #pragma unroll
        for (int s = 0; s < 4; s++) {
            int v  = s * 256 + tid;     // float4 index within tile
            int r  = v >> 3;            // 8 float4 per row (32 floats)
            int c4 = v & 7;
            float4 av = *reinterpret_cast<const float4*>(
                &A[(size_t)(row0 + r) * K + k0 + c4 * 4]);
            As[(c4 * 4 + 0) * BM + r] = av.x;
            As[(c4 * 4 + 1) * BM + r] = av.y;
            As[(c4 * 4 + 2) * BM + r] = av.z;
            As[(c4 * 4 + 3) * BM + r] = av.w;
            float4 bv = *reinterpret_cast<const float4*>(
                &B[(size_t)(col0 + r) * K + k0 + c4 * 4]);
            Bs[(c4 * 4 + 0) * BN + r] = bv.x;
            Bs[(c4 * 4 + 1) * BN + r] = bv.y;
            Bs[(c4 * 4 + 2) * BN + r] = bv.z;
            Bs[(c4 * 4 + 3) * BN + r] = bv.w;
        }
        __syncthreads();

        #pragma unroll
        for (int kk = 0; kk < BK; kk++) {
            float4 a0 = *reinterpret_cast<const float4*>(&As[kk * BM + ty * 8]);
            float4 a1 = *reinterpret_cast<const float4*>(&As[kk * BM + ty * 8 + 4]);
            float4 b0 = *reinterpret_cast<const float4*>(&Bs[kk * BN + tx * 8]);
            float4 b1 = *reinterpret_cast<const float4*>(&Bs[kk * BN + tx * 8 + 4]);
            float a[8] = {a0.x, a0.y, a0.z, a0.w, a1.x, a1.y, a1.z, a1.w};
            float b[8] = {b0.x, b0.y, b0.z, b0.w, b1.x, b1.y, b1.z, b1.w};
            #pragma unroll
            for (int i = 0; i < 8; i++)
                #pragma unroll
                for (int j = 0; j < 8; j++)
                    acc[i][j] = fmaf(a[i], b[j], acc[i][j]);
        }
        __syncthreads();
    }

    // Write back (two float4 per row)
    #pragma unroll
    for (int i = 0; i < 8; i++) {
        int row = row0 + ty * 8 + i;
        float4 o0 = make_float4(acc[i][0], acc[i][1], acc[i][2], acc[i][3]);
        float4 o1 = make_float4(acc[i][4], acc[i][5], acc[i][6], acc[i][7]);
        *reinterpret_cast<float4*>(&C[(size_t)row * N + col0 + tx * 8])     = o0;
        *reinterpret_cast<float4*>(&C[(size_t)row * N + col0 + tx * 8 + 4]) = o1;
    }
}

// ---------------------------------------------------------------------------
// Flash attention (fp32, causal). One block = 64 query rows of one (b,h).
// BM=BN=64, D=64. 256 threads (16x16), each owns 4x4 of S and O.
// Dynamic SMEM: Qst[64][64] + Kst[64][64] + Vs[64][64] + Ps[64][64] = 64 KB.
// ---------------------------------------------------------------------------
__global__ __launch_bounds__(256) void flash_attn_kernel(
    const float* __restrict__ Q, const float* __restrict__ K,
    const float* __restrict__ V, float* __restrict__ O)
{
    constexpr int BM = 64, BN = 64, D = DH;
    extern __shared__ float sm[];
    float* Qst = sm;                    // [D][BM]  (transposed)
    float* Kst = Qst + D * BM;          // [D][BN]  (transposed)
    float* Vs  = Kst + D * BN;          // [BN][D]  (row-major)
    float* Ps  = Vs  + BN * D;          // [BM][BN] (row-major)

    const int tid = threadIdx.x;
    const int tx  = tid & 15;
    const int ty  = tid >> 4;
    const int qb  = blockIdx.x;         // 0..31
    const int bh  = blockIdx.y;         // 0..63
    const int b   = bh >> 4;
    const int h   = bh & 15;

    const float* Qg = Q + (size_t)b * SEQ * DM + h * DH;
    const float* Kg = K + (size_t)b * SEQ * DM + h * DH;
    const float* Vg = V + (size_t)b * SEQ * DM + h * DH;
    float*       Og = O + (size_t)b * SEQ * DM + h * DH;

    // Load Q tile (scaled by 1/sqrt(d_h)=0.125), store transposed.
    #pragma unroll
    for (int s = 0; s < 4; s++) {
        int v  = s * 256 + tid;         // float4 index in 64x64 tile (16 f4 per row)
        int r  = v >> 4;
        int c4 = v & 15;
        float4 q = *reinterpret_cast<const float4*>(
            &Qg[(size_t)(qb * BM + r) * DM + c4 * 4]);
        Qst[(c4 * 4 + 0) * BM + r] = q.x * 0.125f;
        Qst[(c4 * 4 + 1) * BM + r] = q.y * 0.125f;
        Qst[(c4 * 4 + 2) * BM + r] = q.z * 0.125f;
        Qst[(c4 * 4 + 3) * BM + r] = q.w * 0.125f;
    }

    float m[4], l[4], o[4][4];
    #pragma unroll
    for (int i = 0; i < 4; i++) {
        m[i] = -1e30f; l[i] = 0.0f;
        #pragma unroll
        for (int j = 0; j < 4; j++) o[i][j] = 0.0f;
    }
    __syncthreads();

    for (int kb = 0; kb <= qb; kb++) {
        // Load K (transposed) and V (row-major) tiles.
        #pragma unroll
        for (int s = 0; s < 4; s++) {
            int v  = s * 256 + tid;
            int r  = v >> 4;
            int c4 = v & 15;
            float4 kv = *reinterpret_cast<const float4*>(
                &Kg[(size_t)(kb * BN + r) * DM + c4 * 4]);
            Kst[(c4 * 4 + 0) * BN + r] = kv.x;
            Kst[(c4 * 4 + 1) * BN + r] = kv.y;
            Kst[(c4 * 4 + 2) * BN + r] = kv.z;
            Kst[(c4 * 4 + 3) * BN + r] = kv.w;
            float4 vv = *reinterpret_cast<const float4*>(
                &Vg[(size_t)(kb * BN + r) * DM + c4 * 4]);
            *reinterpret_cast<float4*>(&Vs[r * D + c4 * 4]) = vv;
        }
        __syncthreads();

        // S = (Q*scale) @ K^T  -> 4x4 per thread
        float sacc[4][4];
        #pragma unroll
        for (int i = 0; i < 4; i++)
            #pragma unroll
            for (int j = 0; j < 4; j++) sacc[i][j] = 0.0f;

        #pragma unroll 8
        for (int d = 0; d < D; d++) {
            float4 a = *reinterpret_cast<const float4*>(&Qst[d * BM + ty * 4]);
            float4 bq = *reinterpret_cast<const float4*>(&Kst[d * BN + tx * 4]);
            float av[4] = {a.x, a.y, a.z, a.w};
            float bv[4] = {bq.x, bq.y, bq.z, bq.w};
            #pragma unroll
            for (int i = 0; i < 4; i++)
                #pragma unroll
                for (int j = 0; j < 4; j++)
                    sacc[i][j] = fmaf(av[i], bv[j], sacc[i][j]);
        }

        // Causal mask on diagonal block
        if (kb == qb) {
            #pragma unroll
            for (int i = 0; i < 4; i++)
                #pragma unroll
                for (int j = 0; j < 4; j++)
                    if (tx * 4 + j > ty * 4 + i) sacc[i][j] = -1e30f;
        }

        // Online softmax: row max over 16 tx lanes (lanes [ty&1]*16+tx within warp)
        float alpha[4];
        #pragma unroll
        for (int i = 0; i < 4; i++) {
            float mx = fmaxf(fmaxf(sacc[i][0], sacc[i][1]),
                             fmaxf(sacc[i][2], sacc[i][3]));
            #pragma unroll
            for (int w = 1; w < 16; w <<= 1)
                mx = fmaxf(mx, __shfl_xor_sync(0xffffffffu, mx, w));
            float mnew = fmaxf(m[i], mx);
            alpha[i] = __expf(m[i] - mnew);
            float rs = 0.0f;
            #pragma unroll
            for (int j = 0; j < 4; j++) {
                float p = __expf(sacc[i][j] - mnew);
                sacc[i][j] = p;
                rs += p;
            }
            #pragma unroll
            for (int w = 1; w < 16; w <<= 1)
                rs += __shfl_xor_sync(0xffffffffu, rs, w);
            l[i] = l[i] * alpha[i] + rs;
            m[i] = mnew;
            #pragma unroll
            for (int j = 0; j < 4; j++) o[i][j] *= alpha[i];
        }

        // Stage P to SMEM for the P@V GEMM
        #pragma unroll
        for (int i = 0; i < 4; i++) {
            float4 pv = make_float4(sacc[i][0], sacc[i][1], sacc[i][2], sacc[i][3]);
            *reinterpret_cast<float4*>(&Ps[(ty * 4 + i) * BN + tx * 4]) = pv;
        }
        __syncthreads();

        // O += P @ V
        #pragma unroll 4
        for (int k = 0; k < BN; k++) {
            float4 b4 = *reinterpret_cast<const float4*>(&Vs[k * D + tx * 4]);
            #pragma unroll
            for (int i = 0; i < 4; i++) {
                float p = Ps[(ty * 4 + i) * BN + k];
                o[i][0] = fmaf(p, b4.x, o[i][0]);
                o[i][1] = fmaf(p, b4.y, o[i][1]);
                o[i][2] = fmaf(p, b4.z, o[i][2]);
                o[i][3] = fmaf(p, b4.w, o[i][3]);
            }
        }
        __syncthreads();
    }

    // Epilogue: normalize and write to Temp layout [b, s, h*64 + d]
    #pragma unroll
    for (int i = 0; i < 4; i++) {
        float inv = 1.0f / l[i];
        float4 ov = make_float4(o[i][0] * inv, o[i][1] * inv,
                                o[i][2] * inv, o[i][3] * inv);
        int row = qb * BM + ty * 4 + i;
        *reinterpret_cast<float4*>(&Og[(size_t)row * DM + tx * 4]) = ov;
    }
}

// ---------------------------------------------------------------------------
// Launcher
// ---------------------------------------------------------------------------
extern "C" void kernel_launch(void* const* d_in, const int* in_sizes, int n_in,
                              void* d_out, int out_size)
{
    const float* x   = (const float*)d_in[0];
    const float* W_q = (const float*)d_in[1];
    const float* W_k = (const float*)d_in[2];
    const float* W_v = (const float*)d_in[3];
    const float* W_o = (const float*)d_in[4];
    float* out = (float*)d_out;

    float *Qb, *Kb, *Vb, *Tb;
    cudaGetSymbolAddress((void**)&Qb, g_Q);
    cudaGetSymbolAddress((void**)&Kb, g_K);
    cudaGetSymbolAddress((void**)&Vb, g_V);
    cudaGetSymbolAddress((void**)&Tb, g_T);

    dim3 gemm_grid(DM / 128, ROWS / 128);   // (8, 64)
    sgemm_nt_kernel<<<gemm_grid, 256>>>(x, W_q, Qb, ROWS, DM, DM);
    sgemm_nt_kernel<<<gemm_grid, 256>>>(x, W_k, Kb, ROWS, DM, DM);
    sgemm_nt_kernel<<<gemm_grid, 256>>>(x, W_v, Vb, ROWS, DM, DM);

    static int smem_set = 0;
    (void)smem_set;
    cudaFuncSetAttribute(flash_attn_kernel,
                         cudaFuncAttributeMaxDynamicSharedMemorySize, 64 * 1024);
    dim3 attn_grid(SEQ / 64, BATCH * NH);   // (32, 64)
    flash_attn_kernel<<<attn_grid, 256, 64 * 1024>>>(Qb, Kb, Vb, Tb);

    sgemm_nt_kernel<<<gemm_grid, 256>>>(Tb, W_o, out, ROWS, DM, DM);
}

// round 3
// speedup vs baseline: 1.6712x; 1.6712x over previous
#include <cuda_runtime.h>
#include <cuda_bf16.h>
#include <cstdint>

// Problem constants
static constexpr int BATCH = 4;
static constexpr int SEQ   = 2048;
static constexpr int DM    = 1024;
static constexpr int NH    = 16;
static constexpr int DH    = 64;
static constexpr int ROWS  = BATCH * SEQ;        // 8192
static constexpr size_t NX = (size_t)ROWS * DM;  // 8388608
static constexpr size_t NW = (size_t)DM * DM;    // 1048576

// Scratch (device globals: allocation-free)
__device__ float g_Q[NX];
__device__ float g_K[NX];
__device__ float g_V[NX];
__device__ float g_T[NX];
__device__ __nv_bfloat16 g_xh[NX];
__device__ __nv_bfloat16 g_xl[NX];
__device__ __nv_bfloat16 g_Wh[4 * NW];
__device__ __nv_bfloat16 g_Wl[4 * NW];

// ---------------------------------------------------------------------------
// Helpers (all non-'a'-gated: ldmatrix sm_75+, mma.sync bf16 sm_80+, cp.async sm_80+)
// ---------------------------------------------------------------------------
__device__ __forceinline__ uint32_t smem_u32(const void* p) {
    uint32_t a;
    asm("{ .reg .u64 t; cvta.to.shared.u64 t, %1; cvt.u32.u64 %0, t; }"
        : "=r"(a) : "l"(p));
    return a;
}
__device__ __forceinline__ uint32_t sw128(uint32_t off) {
    return off ^ ((off >> 3) & 0x70);
}
__device__ __forceinline__ void cp_async16(uint32_t saddr, const void* gaddr) {
    asm volatile("cp.async.cg.shared.global [%0], [%1], 16;"
                 :: "r"(saddr), "l"(gaddr));
}
#define CP_COMMIT() asm volatile("cp.async.commit_group;")
#define CP_WAIT(n)  asm volatile("cp.async.wait_group %0;" :: "n"(n))

__device__ __forceinline__ void ldsm_x4(uint32_t (&r)[4], uint32_t addr) {
    asm volatile("ldmatrix.sync.aligned.m8n8.x4.shared.b16 {%0,%1,%2,%3}, [%4];"
                 : "=r"(r[0]), "=r"(r[1]), "=r"(r[2]), "=r"(r[3]) : "r"(addr));
}
__device__ __forceinline__ void mma_bf16(float (&d)[4], const uint32_t (&a)[4],
                                         const uint32_t* b) {
    asm volatile(
        "mma.sync.aligned.m16n8k16.row.col.f32.bf16.bf16.f32 "
        "{%0,%1,%2,%3}, {%4,%5,%6,%7}, {%8,%9}, {%0,%1,%2,%3};"
        : "+f"(d[0]), "+f"(d[1]), "+f"(d[2]), "+f"(d[3])
        : "r"(a[0]), "r"(a[1]), "r"(a[2]), "r"(a[3]), "r"(b[0]), "r"(b[1]));
}

// ---------------------------------------------------------------------------
// fp32 -> (hi, lo) bf16 split, vectorized by 4
// ---------------------------------------------------------------------------
__global__ __launch_bounds__(256) void split_bf16_kernel(
    const float* __restrict__ src, __nv_bfloat16* __restrict__ hi,
    __nv_bfloat16* __restrict__ lo, int n4)
{
    int i = blockIdx.x * blockDim.x + threadIdx.x;
    if (i >= n4) return;
    float4 v = reinterpret_cast<const float4*>(src)[i];
    __nv_bfloat16 h0 = __float2bfloat16(v.x);
    __nv_bfloat16 h1 = __float2bfloat16(v.y);
    __nv_bfloat16 h2 = __float2bfloat16(v.z);
    __nv_bfloat16 h3 = __float2bfloat16(v.w);
    __nv_bfloat16 l0 = __float2bfloat16(v.x - __bfloat162float(h0));
    __nv_bfloat16 l1 = __float2bfloat16(v.y - __bfloat162float(h1));
    __nv_bfloat16 l2 = __float2bfloat16(v.z - __bfloat162float(h2));
    __nv_bfloat16 l3 = __float2bfloat16(v.w - __bfloat162float(h3));
    __nv_bfloat162 hp0 = __halves2bfloat162(h0, h1);
    __nv_bfloat162 hp1 = __halves2bfloat162(h2, h3);
    __nv_bfloat162 lp0 = __halves2bfloat162(l0, l1);
    __nv_bfloat162 lp1 = __halves2bfloat162(l2, l3);
    uint2 hv, lv;
    hv.x = *reinterpret_cast<uint32_t*>(&hp0); hv.y = *reinterpret_cast<uint32_t*>(&hp1);
    lv.x = *reinterpret_cast<uint32_t*>(&lp0); lv.y = *reinterpret_cast<uint32_t*>(&lp1);
    reinterpret_cast<uint2*>(hi)[i] = hv;
    reinterpret_cast<uint2*>(lo)[i] = lv;
}

// ---------------------------------------------------------------------------
// bf16-split GEMM (NT) via mma.sync: C[M,N] = A[M,K] @ B[N,K]^T, fp32-class accuracy.
// 128x128 CTA tile, BK=32 bf16, 3-stage cp.async pipeline, 256 threads.
// SMEM row packs [A_hi 64B | A_lo 64B] = 128B SW128 atom.
// Warps: 2(m) x 4(n); warp tile 64x32 = 4x4 m16n8k16 tiles.
// ---------------------------------------------------------------------------
static constexpr int GBK         = 32;                  // bf16 K per stage
static constexpr int TILE_B      = 128 * 128;           // 16384 bytes (A or B tile)
static constexpr int STAGE_B     = 2 * TILE_B;          // 32768
static constexpr int GSTAGES     = 3;
static constexpr int GEMM_SMEM   = GSTAGES * STAGE_B;   // 98304

__global__ __launch_bounds__(256, 1) void gemm_mma_split_kernel(
    const __nv_bfloat16* __restrict__ Ah, const __nv_bfloat16* __restrict__ Al,
    const __nv_bfloat16* __restrict__ Bh, const __nv_bfloat16* __restrict__ Bl,
    float* __restrict__ C, int M, int N, int K)
{
    extern __shared__ char smem[];
    const uint32_t sbase = smem_u32(smem);

    const int tid   = threadIdx.x;
    const int wid   = tid >> 5;
    const int lane  = tid & 31;
    const int warpm = wid >> 2;          // 0..1
    const int warpn = wid & 3;           // 0..3
    const int row0  = blockIdx.y * 128;
    const int col0  = blockIdx.x * 128;
    const int NKT   = K / GBK;           // 32

    // loader: per thread 4 chunks of A + 4 of B (16B each)
    auto load_stage = [&](int s, int kt) {
        const uint32_t As = sbase + s * STAGE_B;
        const uint32_t Bs = As + TILE_B;
        const size_t kofs = (size_t)kt * GBK;
        const __nv_bfloat16* Ah0 = Ah + (size_t)row0 * K + kofs;
        const __nv_bfloat16* Al0 = Al + (size_t)row0 * K + kofs;
        const __nv_bfloat16* Bh0 = Bh + (size_t)col0 * K + kofs;
        const __nv_bfloat16* Bl0 = Bl + (size_t)col0 * K + kofs;
        #pragma unroll
        for (int t = 0; t < 4; t++) {
            int v = t * 256 + tid;        // 0..1023
            int r = v >> 3;               // row 0..127
            int c = v & 7;                // 16B chunk 0..7 (0-3 hi, 4-7 lo)
            uint32_t soff = sw128((uint32_t)(r * 128 + c * 16));
            const __nv_bfloat16* ga =
                (c < 4 ? Ah0 : Al0) + (size_t)r * K + (c & 3) * 8;
            cp_async16(As + soff, ga);
            const __nv_bfloat16* gb =
                (c < 4 ? Bh0 : Bl0) + (size_t)r * K + (c & 3) * 8;
            cp_async16(Bs + soff, gb);
        }
    };

    float acc[4][4][4];
    #pragma unroll
    for (int i = 0; i < 4; i++)
        #pragma unroll
        for (int j = 0; j < 4; j++)
            #pragma unroll
            for (int k = 0; k < 4; k++) acc[i][j][k] = 0.0f;

    load_stage(0, 0); CP_COMMIT();
    load_stage(1, 1); CP_COMMIT();

    for (int kt = 0; kt < NKT; kt++) {
        CP_WAIT(1);
        __syncthreads();
        if (kt + 2 < NKT) load_stage((kt + 2) % GSTAGES, kt + 2);
        CP_COMMIT();

        const int s = kt % GSTAGES;
        const uint32_t As = sbase + s * STAGE_B;
        const uint32_t Bs = As + TILE_B;

        #pragma unroll
        for (int kc = 0; kc < 2; kc++) {
            uint32_t afr[2][4][4];   // [term][mt][4]
            uint32_t bfr[2][4][2];   // [term][nt][2]
            #pragma unroll
            for (int term = 0; term < 2; term++) {
                const int j = term * 4 + kc * 2;
                #pragma unroll
                for (int mt = 0; mt < 4; mt++) {
                    int row   = warpm * 64 + mt * 16 + (lane & 15);
                    int chunk = j + (lane >> 4);
                    ldsm_x4(afr[term][mt], As + sw128((uint32_t)(row * 128 + chunk * 16)));
                }
                #pragma unroll
                for (int p = 0; p < 2; p++) {
                    int row   = warpn * 32 + p * 16 + ((lane >> 4) << 3) + (lane & 7);
                    int chunk = j + ((lane >> 3) & 1);
                    uint32_t t4[4];
                    ldsm_x4(t4, Bs + sw128((uint32_t)(row * 128 + chunk * 16)));
                    bfr[term][p * 2][0]     = t4[0];
                    bfr[term][p * 2][1]     = t4[1];
                    bfr[term][p * 2 + 1][0] = t4[2];
                    bfr[term][p * 2 + 1][1] = t4[3];
                }
            }
            #pragma unroll
            for (int mt = 0; mt < 4; mt++)
                #pragma unroll
                for (int nt = 0; nt < 4; nt++) {
                    mma_bf16(acc[mt][nt], afr[0][mt], bfr[0][nt]);  // hi*hi
                    mma_bf16(acc[mt][nt], afr[0][mt], bfr[1][nt]);  // hi*lo
                    mma_bf16(acc[mt][nt], afr[1][mt], bfr[0][nt]);  // lo*hi
                }
        }
        __syncthreads();
    }

    // Epilogue: fragment layout -> C
    const int g = lane >> 2;         // group 0..7
    const int t = lane & 3;          // 0..3
    #pragma unroll
    for (int mt = 0; mt < 4; mt++) {
        #pragma unroll
        for (int nt = 0; nt < 4; nt++) {
            int row = row0 + warpm * 64 + mt * 16 + g;
            int col = col0 + warpn * 32 + nt * 8 + t * 2;
            float2 v0 = make_float2(acc[mt][nt][0], acc[mt][nt][1]);
            float2 v1 = make_float2(acc[mt][nt][2], acc[mt][nt][3]);
            *reinterpret_cast<float2*>(&C[(size_t)row * N + col])       = v0;
            *reinterpret_cast<float2*>(&C[(size_t)(row + 8) * N + col]) = v1;
        }
    }
}

// ---------------------------------------------------------------------------
// Flash attention (fp32, causal) — unchanged from R1 (proven correct)
// ---------------------------------------------------------------------------
__global__ __launch_bounds__(256) void flash_attn_kernel(
    const float* __restrict__ Q, const float* __restrict__ K,
    const float* __restrict__ V, float* __restrict__ O)
{
    constexpr int BM = 64, BN = 64, D = DH;
    extern __shared__ float sm[];
    float* Qst = sm;
    float* Kst = Qst + D * BM;
    float* Vs  = Kst + D * BN;
    float* Ps  = Vs  + BN * D;

    const int tid = threadIdx.x;
    const int tx  = tid & 15;
    const int ty  = tid >> 4;
    const int qb  = blockIdx.x;
    const int bh  = blockIdx.y;
    const int b   = bh >> 4;
    const int h   = bh & 15;

    const float* Qg = Q + (size_t)b * SEQ * DM + h * DH;
    const float* Kg = K + (size_t)b * SEQ * DM + h * DH;
    const float* Vg = V + (size_t)b * SEQ * DM + h * DH;
    float*       Og = O + (size_t)b * SEQ * DM + h * DH;

    #pragma unroll
    for (int s = 0; s < 4; s++) {
        int v  = s * 256 + tid;
        int r  = v >> 4;
        int c4 = v & 15;
        float4 q = *reinterpret_cast<const float4*>(
            &Qg[(size_t)(qb * BM + r) * DM + c4 * 4]);
        Qst[(c4 * 4 + 0) * BM + r] = q.x * 0.125f;
        Qst[(c4 * 4 + 1) * BM + r] = q.y * 0.125f;
        Qst[(c4 * 4 + 2) * BM + r] = q.z * 0.125f;
        Qst[(c4 * 4 + 3) * BM + r] = q.w * 0.125f;
    }

    float m[4], l[4], o[4][4];
    #pragma unroll
    for (int i = 0; i < 4; i++) {
        m[i] = -1e30f; l[i] = 0.0f;
        #pragma unroll
        for (int j = 0; j < 4; j++) o[i][j] = 0.0f;
    }
    __syncthreads();

    for (int kb = 0; kb <= qb; kb++) {
        #pragma unroll
        for (int s = 0; s < 4; s++) {
            int v  = s * 256 + tid;
            int r  = v >> 4;
            int c4 = v & 15;
            float4 kv = *reinterpret_cast<const float4*>(
                &Kg[(size_t)(kb * BN + r) * DM + c4 * 4]);
            Kst[(c4 * 4 + 0) * BN + r] = kv.x;
            Kst[(c4 * 4 + 1) * BN + r] = kv.y;
            Kst[(c4 * 4 + 2) * BN + r] = kv.z;
            Kst[(c4 * 4 + 3) * BN + r] = kv.w;
            float4 vv = *reinterpret_cast<const float4*>(
                &Vg[(size_t)(kb * BN + r) * DM + c4 * 4]);
            *reinterpret_cast<float4*>(&Vs[r * D + c4 * 4]) = vv;
        }
        __syncthreads();

        float sacc[4][4];
        #pragma unroll
        for (int i = 0; i < 4; i++)
            #pragma unroll
            for (int j = 0; j < 4; j++) sacc[i][j] = 0.0f;

        #pragma unroll 8
        for (int d = 0; d < D; d++) {
            float4 a = *reinterpret_cast<const float4*>(&Qst[d * BM + ty * 4]);
            float4 bq = *reinterpret_cast<const float4*>(&Kst[d * BN + tx * 4]);
            float av[4] = {a.x, a.y, a.z, a.w};
            float bv[4] = {bq.x, bq.y, bq.z, bq.w};
            #pragma unroll
            for (int i = 0; i < 4; i++)
                #pragma unroll
                for (int j = 0; j < 4; j++)
                    sacc[i][j] = fmaf(av[i], bv[j], sacc[i][j]);
        }

        if (kb == qb) {
            #pragma unroll
            for (int i = 0; i < 4; i++)
                #pragma unroll
                for (int j = 0; j < 4; j++)
                    if (tx * 4 + j > ty * 4 + i) sacc[i][j] = -1e30f;
        }

        float alpha[4];
        #pragma unroll
        for (int i = 0; i < 4; i++) {
            float mx = fmaxf(fmaxf(sacc[i][0], sacc[i][1]),
                             fmaxf(sacc[i][2], sacc[i][3]));
            #pragma unroll
            for (int w = 1; w < 16; w <<= 1)
                mx = fmaxf(mx, __shfl_xor_sync(0xffffffffu, mx, w));
            float mnew = fmaxf(m[i], mx);
            alpha[i] = __expf(m[i] - mnew);
            float rs = 0.0f;
            #pragma unroll
            for (int j = 0; j < 4; j++) {
                float p = __expf(sacc[i][j] - mnew);
                sacc[i][j] = p;
                rs += p;
            }
            #pragma unroll
            for (int w = 1; w < 16; w <<= 1)
                rs += __shfl_xor_sync(0xffffffffu, rs, w);
            l[i] = l[i] * alpha[i] + rs;
            m[i] = mnew;
            #pragma unroll
            for (int j = 0; j < 4; j++) o[i][j] *= alpha[i];
        }

        #pragma unroll
        for (int i = 0; i < 4; i++) {
            float4 pv = make_float4(sacc[i][0], sacc[i][1], sacc[i][2], sacc[i][3]);
            *reinterpret_cast<float4*>(&Ps[(ty * 4 + i) * BN + tx * 4]) = pv;
        }
        __syncthreads();

        #pragma unroll 4
        for (int k = 0; k < BN; k++) {
            float4 b4 = *reinterpret_cast<const float4*>(&Vs[k * D + tx * 4]);
            #pragma unroll
            for (int i = 0; i < 4; i++) {
                float p = Ps[(ty * 4 + i) * BN + k];
                o[i][0] = fmaf(p, b4.x, o[i][0]);
                o[i][1] = fmaf(p, b4.y, o[i][1]);
                o[i][2] = fmaf(p, b4.z, o[i][2]);
                o[i][3] = fmaf(p, b4.w, o[i][3]);
            }
        }
        __syncthreads();
    }

    #pragma unroll
    for (int i = 0; i < 4; i++) {
        float inv = 1.0f / l[i];
        float4 ov = make_float4(o[i][0] * inv, o[i][1] * inv,
                                o[i][2] * inv, o[i][3] * inv);
        int row = qb * BM + ty * 4 + i;
        *reinterpret_cast<float4*>(&Og[(size_t)row * DM + tx * 4]) = ov;
    }
}

// ---------------------------------------------------------------------------
// Launcher
// ---------------------------------------------------------------------------
extern "C" void kernel_launch(void* const* d_in, const int* in_sizes, int n_in,
                              void* d_out, int out_size)
{
    const float* x   = (const float*)d_in[0];
    const float* W_q = (const float*)d_in[1];
    const float* W_k = (const float*)d_in[2];
    const float* W_v = (const float*)d_in[3];
    const float* W_o = (const float*)d_in[4];
    float* out = (float*)d_out;

    float *Qb, *Kb, *Vb, *Tb;
    __nv_bfloat16 *xh, *xl, *Wh, *Wl;
    cudaGetSymbolAddress((void**)&Qb, g_Q);
    cudaGetSymbolAddress((void**)&Kb, g_K);
    cudaGetSymbolAddress((void**)&Vb, g_V);
    cudaGetSymbolAddress((void**)&Tb, g_T);
    cudaGetSymbolAddress((void**)&xh, g_xh);
    cudaGetSymbolAddress((void**)&xl, g_xl);
    cudaGetSymbolAddress((void**)&Wh, g_Wh);
    cudaGetSymbolAddress((void**)&Wl, g_Wl);

    cudaFuncSetAttribute(gemm_mma_split_kernel,
                         cudaFuncAttributeMaxDynamicSharedMemorySize, GEMM_SMEM);
    cudaFuncSetAttribute(flash_attn_kernel,
                         cudaFuncAttributeMaxDynamicSharedMemorySize, 64 * 1024);

    // Split inputs to bf16 hi/lo
    const int nx4 = (int)(NX / 4), nw4 = (int)(NW / 4);
    split_bf16_kernel<<<(nx4 + 255) / 256, 256>>>(x, xh, xl, nx4);
    split_bf16_kernel<<<(nw4 + 255) / 256, 256>>>(W_q, Wh + 0 * NW, Wl + 0 * NW, nw4);
    split_bf16_kernel<<<(nw4 + 255) / 256, 256>>>(W_k, Wh + 1 * NW, Wl + 1 * NW, nw4);
    split_bf16_kernel<<<(nw4 + 255) / 256, 256>>>(W_v, Wh + 2 * NW, Wl + 2 * NW, nw4);
    split_bf16_kernel<<<(nw4 + 255) / 256, 256>>>(W_o, Wh + 3 * NW, Wl + 3 * NW, nw4);

    dim3 gemm_grid(DM / 128, ROWS / 128);   // (8, 64)
    gemm_mma_split_kernel<<<gemm_grid, 256, GEMM_SMEM>>>(
        xh, xl, Wh + 0 * NW, Wl + 0 * NW, Qb, ROWS, DM, DM);
    gemm_mma_split_kernel<<<gemm_grid, 256, GEMM_SMEM>>>(
        xh, xl, Wh + 1 * NW, Wl + 1 * NW, Kb, ROWS, DM, DM);
    gemm_mma_split_kernel<<<gemm_grid, 256, GEMM_SMEM>>>(
        xh, xl, Wh + 2 * NW, Wl + 2 * NW, Vb, ROWS, DM, DM);

    dim3 attn_grid(SEQ / 64, BATCH * NH);   // (32, 64)
    flash_attn_kernel<<<attn_grid, 256, 64 * 1024>>>(Qb, Kb, Vb, Tb);

    split_bf16_kernel<<<(nx4 + 255) / 256, 256>>>(Tb, xh, xl, nx4);
    gemm_mma_split_kernel<<<gemm_grid, 256, GEMM_SMEM>>>(
        xh, xl, Wh + 3 * NW, Wl + 3 * NW, out, ROWS, DM, DM);
}

// round 4
// speedup vs baseline: 3.1693x; 1.8964x over previous
#include <cuda_runtime.h>
#include <cuda_bf16.h>
#include <cstdint>

// Problem constants
static constexpr int BATCH = 4;
static constexpr int SEQ   = 2048;
static constexpr int DM    = 1024;
static constexpr int NH    = 16;
static constexpr int DH    = 64;
static constexpr int ROWS  = BATCH * SEQ;        // 8192
static constexpr size_t NX = (size_t)ROWS * DM;  // 8388608
static constexpr size_t NW = (size_t)DM * DM;    // 1048576

// Scratch (device globals: allocation-free)
__device__ __nv_bfloat16 g_xh[NX];
__device__ __nv_bfloat16 g_xl[NX];
__device__ __nv_bfloat16 g_Wh[4 * NW];
__device__ __nv_bfloat16 g_Wl[4 * NW];
__device__ __nv_bfloat16 g_qh[NX];
__device__ __nv_bfloat16 g_ql[NX];
__device__ __nv_bfloat16 g_kh[NX];
__device__ __nv_bfloat16 g_kl[NX];
__device__ __nv_bfloat16 g_vh[NX];
__device__ __nv_bfloat16 g_vl[NX];
__device__ __nv_bfloat16 g_th[NX];
__device__ __nv_bfloat16 g_tl[NX];

// ---------------------------------------------------------------------------
// Helpers (non-'a'-gated: ldmatrix sm_75+, mma.sync bf16 sm_80+, cp.async sm_80+)
// ---------------------------------------------------------------------------
__device__ __forceinline__ uint32_t smem_u32(const void* p) {
    uint32_t a;
    asm("{ .reg .u64 t; cvta.to.shared.u64 t, %1; cvt.u32.u64 %0, t; }"
        : "=r"(a) : "l"(p));
    return a;
}
__device__ __forceinline__ uint32_t sw128(uint32_t off) {
    return off ^ ((off >> 3) & 0x70);
}
__device__ __forceinline__ void cp_async16(uint32_t saddr, const void* gaddr) {
    asm volatile("cp.async.cg.shared.global [%0], [%1], 16;"
                 :: "r"(saddr), "l"(gaddr));
}
#define CP_COMMIT() asm volatile("cp.async.commit_group;")
#define CP_WAIT(n)  asm volatile("cp.async.wait_group %0;" :: "n"(n))

__device__ __forceinline__ void ldsm_x4(uint32_t (&r)[4], uint32_t addr) {
    asm volatile("ldmatrix.sync.aligned.m8n8.x4.shared.b16 {%0,%1,%2,%3}, [%4];"
                 : "=r"(r[0]), "=r"(r[1]), "=r"(r[2]), "=r"(r[3]) : "r"(addr));
}
__device__ __forceinline__ void ldsm_x4_t(uint32_t (&r)[4], uint32_t addr) {
    asm volatile("ldmatrix.sync.aligned.m8n8.x4.trans.shared.b16 {%0,%1,%2,%3}, [%4];"
                 : "=r"(r[0]), "=r"(r[1]), "=r"(r[2]), "=r"(r[3]) : "r"(addr));
}
__device__ __forceinline__ void mma_bf16(float (&d)[4], const uint32_t (&a)[4],
                                         const uint32_t* b) {
    asm volatile(
        "mma.sync.aligned.m16n8k16.row.col.f32.bf16.bf16.f32 "
        "{%0,%1,%2,%3}, {%4,%5,%6,%7}, {%8,%9}, {%0,%1,%2,%3};"
        : "+f"(d[0]), "+f"(d[1]), "+f"(d[2]), "+f"(d[3])
        : "r"(a[0]), "r"(a[1]), "r"(a[2]), "r"(a[3]), "r"(b[0]), "r"(b[1]));
}

// split a pair of fp32 into (hi,lo) bf16x2 and store packed
__device__ __forceinline__ void split_store_pair(float a, float b,
                                                 __nv_bfloat16* hp, __nv_bfloat16* lp) {
    __nv_bfloat162 h2 = __float22bfloat162_rn(make_float2(a, b));
    float2 hf = __bfloat1622float2(h2);
    __nv_bfloat162 l2 = __float22bfloat162_rn(make_float2(a - hf.x, b - hf.y));
    *reinterpret_cast<uint32_t*>(hp) = *reinterpret_cast<const uint32_t*>(&h2);
    *reinterpret_cast<uint32_t*>(lp) = *reinterpret_cast<const uint32_t*>(&l2);
}
// split a pair of fp32 into (hi,lo) bf16x2 registers
__device__ __forceinline__ void pack_split(float a, float b, uint32_t& ph, uint32_t& pl) {
    __nv_bfloat162 h2 = __float22bfloat162_rn(make_float2(a, b));
    float2 hf = __bfloat1622float2(h2);
    __nv_bfloat162 l2 = __float22bfloat162_rn(make_float2(a - hf.x, b - hf.y));
    ph = *reinterpret_cast<const uint32_t*>(&h2);
    pl = *reinterpret_cast<const uint32_t*>(&l2);
}

// ---------------------------------------------------------------------------
// fp32 -> (hi, lo) bf16 split, vectorized by 4
// ---------------------------------------------------------------------------
__global__ __launch_bounds__(256) void split_bf16_kernel(
    const float* __restrict__ src, __nv_bfloat16* __restrict__ hi,
    __nv_bfloat16* __restrict__ lo, int n4)
{
    int i = blockIdx.x * blockDim.x + threadIdx.x;
    if (i >= n4) return;
    float4 v = reinterpret_cast<const float4*>(src)[i];
    __nv_bfloat162 h0 = __float22bfloat162_rn(make_float2(v.x, v.y));
    __nv_bfloat162 h1 = __float22bfloat162_rn(make_float2(v.z, v.w));
    float2 f0 = __bfloat1622float2(h0), f1 = __bfloat1622float2(h1);
    __nv_bfloat162 l0 = __float22bfloat162_rn(make_float2(v.x - f0.x, v.y - f0.y));
    __nv_bfloat162 l1 = __float22bfloat162_rn(make_float2(v.z - f1.x, v.w - f1.y));
    uint2 hv, lv;
    hv.x = *reinterpret_cast<uint32_t*>(&h0); hv.y = *reinterpret_cast<uint32_t*>(&h1);
    lv.x = *reinterpret_cast<uint32_t*>(&l0); lv.y = *reinterpret_cast<uint32_t*>(&l1);
    reinterpret_cast<uint2*>(hi)[i] = hv;
    reinterpret_cast<uint2*>(lo)[i] = lv;
}

// ---------------------------------------------------------------------------
// bf16-split GEMM (NT) via mma.sync: C[M,N] = A[M,K] @ B[N,K]^T.
// 128x128 CTA tile, BK=32, 3-stage cp.async pipeline, 256 threads.
// SPLIT_OUT: write C as (hi,lo) bf16 instead of fp32.
// ---------------------------------------------------------------------------
static constexpr int GBK       = 32;
static constexpr int TILE_B    = 128 * 128;
static constexpr int STAGE_B   = 2 * TILE_B;
static constexpr int GSTAGES   = 3;
static constexpr int GEMM_SMEM = GSTAGES * STAGE_B;   // 98304

template <bool SPLIT_OUT>
__global__ __launch_bounds__(256, 1) void gemm_mma_split_kernel(
    const __nv_bfloat16* __restrict__ Ah, const __nv_bfloat16* __restrict__ Al,
    const __nv_bfloat16* __restrict__ Bh, const __nv_bfloat16* __restrict__ Bl,
    float* __restrict__ C, __nv_bfloat16* __restrict__ Ch,
    __nv_bfloat16* __restrict__ Cl, int M, int N, int K)
{
    extern __shared__ char smem[];
    const uint32_t sbase = smem_u32(smem);

    const int tid   = threadIdx.x;
    const int wid   = tid >> 5;
    const int lane  = tid & 31;
    const int warpm = wid >> 2;
    const int warpn = wid & 3;
    const int row0  = blockIdx.y * 128;
    const int col0  = blockIdx.x * 128;
    const int NKT   = K / GBK;

    auto load_stage = [&](int s, int kt) {
        const uint32_t As = sbase + s * STAGE_B;
        const uint32_t Bs = As + TILE_B;
        const size_t kofs = (size_t)kt * GBK;
        const __nv_bfloat16* Ah0 = Ah + (size_t)row0 * K + kofs;
        const __nv_bfloat16* Al0 = Al + (size_t)row0 * K + kofs;
        const __nv_bfloat16* Bh0 = Bh + (size_t)col0 * K + kofs;
        const __nv_bfloat16* Bl0 = Bl + (size_t)col0 * K + kofs;
        #pragma unroll
        for (int t = 0; t < 4; t++) {
            int v = t * 256 + tid;
            int r = v >> 3;
            int c = v & 7;
            uint32_t soff = sw128((uint32_t)(r * 128 + c * 16));
            const __nv_bfloat16* ga = (c < 4 ? Ah0 : Al0) + (size_t)r * K + (c & 3) * 8;
            cp_async16(As + soff, ga);
            const __nv_bfloat16* gb = (c < 4 ? Bh0 : Bl0) + (size_t)r * K + (c & 3) * 8;
            cp_async16(Bs + soff, gb);
        }
    };

    float acc[4][4][4];
    #pragma unroll
    for (int i = 0; i < 4; i++)
        #pragma unroll
        for (int j = 0; j < 4; j++)
            #pragma unroll
            for (int k = 0; k < 4; k++) acc[i][j][k] = 0.0f;

    load_stage(0, 0); CP_COMMIT();
    load_stage(1, 1); CP_COMMIT();

    for (int kt = 0; kt < NKT; kt++) {
        CP_WAIT(1);
        __syncthreads();
        if (kt + 2 < NKT) load_stage((kt + 2) % GSTAGES, kt + 2);
        CP_COMMIT();

        const int s = kt % GSTAGES;
        const uint32_t As = sbase + s * STAGE_B;
        const uint32_t Bs = As + TILE_B;

        #pragma unroll
        for (int kc = 0; kc < 2; kc++) {
            uint32_t afr[2][4][4];
            uint32_t bfr[2][4][2];
            #pragma unroll
            for (int term = 0; term < 2; term++) {
                const int j = term * 4 + kc * 2;
                #pragma unroll
                for (int mt = 0; mt < 4; mt++) {
                    int row   = warpm * 64 + mt * 16 + (lane & 15);
                    int chunk = j + (lane >> 4);
                    ldsm_x4(afr[term][mt], As + sw128((uint32_t)(row * 128 + chunk * 16)));
                }
                #pragma unroll
                for (int p = 0; p < 2; p++) {
                    int row   = warpn * 32 + p * 16 + ((lane >> 4) << 3) + (lane & 7);
                    int chunk = j + ((lane >> 3) & 1);
                    uint32_t t4[4];
                    ldsm_x4(t4, Bs + sw128((uint32_t)(row * 128 + chunk * 16)));
                    bfr[term][p * 2][0]     = t4[0];
                    bfr[term][p * 2][1]     = t4[1];
                    bfr[term][p * 2 + 1][0] = t4[2];
                    bfr[term][p * 2 + 1][1] = t4[3];
                }
            }
            #pragma unroll
            for (int mt = 0; mt < 4; mt++)
                #pragma unroll
                for (int nt = 0; nt < 4; nt++) {
                    mma_bf16(acc[mt][nt], afr[0][mt], bfr[0][nt]);
                    mma_bf16(acc[mt][nt], afr[0][mt], bfr[1][nt]);
                    mma_bf16(acc[mt][nt], afr[1][mt], bfr[0][nt]);
                }
        }
        __syncthreads();
    }

    const int g = lane >> 2;
    const int t = lane & 3;
    #pragma unroll
    for (int mt = 0; mt < 4; mt++) {
        #pragma unroll
        for (int nt = 0; nt < 4; nt++) {
            int row = row0 + warpm * 64 + mt * 16 + g;
            int col = col0 + warpn * 32 + nt * 8 + t * 2;
            if (SPLIT_OUT) {
                split_store_pair(acc[mt][nt][0], acc[mt][nt][1],
                                 Ch + (size_t)row * N + col, Cl + (size_t)row * N + col);
                split_store_pair(acc[mt][nt][2], acc[mt][nt][3],
                                 Ch + (size_t)(row + 8) * N + col,
                                 Cl + (size_t)(row + 8) * N + col);
            } else {
                float2 v0 = make_float2(acc[mt][nt][0], acc[mt][nt][1]);
                float2 v1 = make_float2(acc[mt][nt][2], acc[mt][nt][3]);
                *reinterpret_cast<float2*>(&C[(size_t)row * N + col])       = v0;
                *reinterpret_cast<float2*>(&C[(size_t)(row + 8) * N + col]) = v1;
            }
        }
    }
}

// ---------------------------------------------------------------------------
// Tensor-core flash attention (split-bf16, causal).
// One CTA = 128 query rows of one (b,h). 8 warps, each owns 16 complete rows.
// KV tiles of 64, double-buffered cp.async. Q fragments persistent in regs.
// SMEM: Qh/Ql 32KB + 2 stages x (Kh,Kl,Vh,Vl 8KB each) 64KB = 96KB.
// ---------------------------------------------------------------------------
static constexpr int ATTN_SMEM = 32768 + 2 * 32768;   // 98304

__global__ __launch_bounds__(256, 1) void flash_attn_mma_kernel(
    const __nv_bfloat16* __restrict__ qh, const __nv_bfloat16* __restrict__ ql,
    const __nv_bfloat16* __restrict__ kh, const __nv_bfloat16* __restrict__ kl,
    const __nv_bfloat16* __restrict__ vh, const __nv_bfloat16* __restrict__ vl,
    __nv_bfloat16* __restrict__ th, __nv_bfloat16* __restrict__ tl)
{
    extern __shared__ char smem[];
    const uint32_t sbase = smem_u32(smem);

    const int tid  = threadIdx.x;
    const int wid  = tid >> 5;
    const int lane = tid & 31;
    const int g    = lane >> 2;
    const int t    = lane & 3;

    const int qb = (SEQ / 128 - 1) - blockIdx.x;   // heavy blocks first
    const int bh = blockIdx.y;
    const int b  = bh >> 4;
    const int h  = bh & 15;
    const int q0 = qb * 128;
    const int bofs = b * SEQ;
    const int NT = 2 * qb + 2;                     // kv tiles of 64
    const int rowg = q0 + wid * 16 + g;

    // ---- loaders ----
    auto load_q = [&]() {
        #pragma unroll
        for (int term = 0; term < 2; term++) {
            const __nv_bfloat16* src = term ? ql : qh;
            #pragma unroll
            for (int tt = 0; tt < 4; tt++) {
                int v = tt * 256 + tid;
                int r = v >> 3;
                int c = v & 7;
                cp_async16(sbase + term * 16384 + sw128((uint32_t)(r * 128 + c * 16)),
                           src + (size_t)(bofs + q0 + r) * DM + h * 64 + c * 8);
            }
        }
    };
    auto load_kv = [&](int stage, int kt2) {
        const int kv = kt2 * 64;
        const uint32_t base = sbase + 32768 + stage * 32768;
        const __nv_bfloat16* bufs[4] = {kh, kl, vh, vl};
        #pragma unroll
        for (int buf = 0; buf < 4; buf++) {
            #pragma unroll
            for (int tt = 0; tt < 2; tt++) {
                int v = tt * 256 + tid;
                int r = v >> 3;          // 0..63
                int c = v & 7;
                cp_async16(base + buf * 8192 + sw128((uint32_t)(r * 128 + c * 16)),
                           bufs[buf] + (size_t)(bofs + kv + r) * DM + h * 64 + c * 8);
            }
        }
    };

    load_q();
    load_kv(0, 0); CP_COMMIT();
    load_kv(1, 1); CP_COMMIT();
    CP_WAIT(1);
    __syncthreads();

    // Q fragments (persistent): [term][kstep][4]
    uint32_t qf[2][4][4];
    #pragma unroll
    for (int term = 0; term < 2; term++) {
        const uint32_t qbse = sbase + term * 16384;
        #pragma unroll
        for (int j = 0; j < 4; j++) {
            int row   = wid * 16 + (lane & 15);
            int chunk = j * 2 + (lane >> 4);
            ldsm_x4(qf[term][j], qbse + sw128((uint32_t)(row * 128 + chunk * 16)));
        }
    }

    float m0 = -1e30f, m1 = -1e30f, l0 = 0.0f, l1 = 0.0f;
    float oacc[8][4];
    #pragma unroll
    for (int nt = 0; nt < 8; nt++)
        #pragma unroll
        for (int c = 0; c < 4; c++) oacc[nt][c] = 0.0f;

    for (int kt = 0; kt < NT; kt++) {
        if (kt + 1 < NT) { CP_WAIT(1); } else { CP_WAIT(0); }
        __syncthreads();

        const int kv0 = kt * 64;
        const bool active = kv0 <= q0 + wid * 16 + 15;
        if (active) {
            const uint32_t stg = sbase + 32768 + (kt & 1) * 32768;

            // ---- S = (Qh+Ql) @ (Kh+Kl)^T (3 terms) ----
            float sacc[8][4];
            #pragma unroll
            for (int nt = 0; nt < 8; nt++)
                #pragma unroll
                for (int c = 0; c < 4; c++) sacc[nt][c] = 0.0f;

            #pragma unroll
            for (int j = 0; j < 4; j++) {
                uint32_t kf[2][8][2];
                #pragma unroll
                for (int term = 0; term < 2; term++) {
                    const uint32_t kb = stg + term * 8192;
                    #pragma unroll
                    for (int np = 0; np < 4; np++) {
                        int row   = np * 16 + ((lane >> 4) << 3) + (lane & 7);
                        int chunk = j * 2 + ((lane >> 3) & 1);
                        uint32_t t4[4];
                        ldsm_x4(t4, kb + sw128((uint32_t)(row * 128 + chunk * 16)));
                        kf[term][np * 2][0]     = t4[0];
                        kf[term][np * 2][1]     = t4[1];
                        kf[term][np * 2 + 1][0] = t4[2];
                        kf[term][np * 2 + 1][1] = t4[3];
                    }
                }
                #pragma unroll
                for (int nt = 0; nt < 8; nt++) {
                    mma_bf16(sacc[nt], qf[0][j], kf[0][nt]);
                    mma_bf16(sacc[nt], qf[0][j], kf[1][nt]);
                    mma_bf16(sacc[nt], qf[1][j], kf[0][nt]);
                }
            }

            // ---- scale + causal mask ----
            const bool domask = (kv0 + 63) > (q0 + wid * 16);
            #pragma unroll
            for (int nt = 0; nt < 8; nt++) {
                #pragma unroll
                for (int c = 0; c < 4; c++) {
                    float s = sacc[nt][c] * 0.125f;
                    if (domask) {
                        int col = kv0 + nt * 8 + t * 2 + (c & 1);
                        int row = (c < 2) ? rowg : rowg + 8;
                        if (col > row) s = -1e30f;
                    }
                    sacc[nt][c] = s;
                }
            }

            // ---- online softmax (rows g and g+8; quad reduction) ----
            float mx0 = -1e30f, mx1 = -1e30f;
            #pragma unroll
            for (int nt = 0; nt < 8; nt++) {
                mx0 = fmaxf(mx0, fmaxf(sacc[nt][0], sacc[nt][1]));
                mx1 = fmaxf(mx1, fmaxf(sacc[nt][2], sacc[nt][3]));
            }
            mx0 = fmaxf(mx0, __shfl_xor_sync(0xffffffffu, mx0, 1));
            mx0 = fmaxf(mx0, __shfl_xor_sync(0xffffffffu, mx0, 2));
            mx1 = fmaxf(mx1, __shfl_xor_sync(0xffffffffu, mx1, 1));
            mx1 = fmaxf(mx1, __shfl_xor_sync(0xffffffffu, mx1, 2));
            float mnew0 = fmaxf(m0, mx0), mnew1 = fmaxf(m1, mx1);
            float a0 = __expf(m0 - mnew0), a1 = __expf(m1 - mnew1);
            m0 = mnew0; m1 = mnew1;

            float rs0 = 0.0f, rs1 = 0.0f;
            #pragma unroll
            for (int nt = 0; nt < 8; nt++) {
                float p0 = __expf(sacc[nt][0] - mnew0);
                float p1 = __expf(sacc[nt][1] - mnew0);
                float p2 = __expf(sacc[nt][2] - mnew1);
                float p3 = __expf(sacc[nt][3] - mnew1);
                sacc[nt][0] = p0; sacc[nt][1] = p1;
                sacc[nt][2] = p2; sacc[nt][3] = p3;
                rs0 += p0 + p1; rs1 += p2 + p3;
            }
            rs0 += __shfl_xor_sync(0xffffffffu, rs0, 1);
            rs0 += __shfl_xor_sync(0xffffffffu, rs0, 2);
            rs1 += __shfl_xor_sync(0xffffffffu, rs1, 1);
            rs1 += __shfl_xor_sync(0xffffffffu, rs1, 2);
            l0 = l0 * a0 + rs0;
            l1 = l1 * a1 + rs1;
            #pragma unroll
            for (int nt = 0; nt < 8; nt++) {
                oacc[nt][0] *= a0; oacc[nt][1] *= a0;
                oacc[nt][2] *= a1; oacc[nt][3] *= a1;
            }

            // ---- O += (Ph+Pl) @ (Vh+Vl) (3 terms) ----
            #pragma unroll
            for (int pj = 0; pj < 4; pj++) {
                const float* se = sacc[2 * pj];
                const float* so = sacc[2 * pj + 1];
                uint32_t ph[4], pl[4];
                pack_split(se[0], se[1], ph[0], pl[0]);
                pack_split(se[2], se[3], ph[1], pl[1]);
                pack_split(so[0], so[1], ph[2], pl[2]);
                pack_split(so[2], so[3], ph[3], pl[3]);

                uint32_t vf[2][8][2];
                #pragma unroll
                for (int term = 0; term < 2; term++) {
                    const uint32_t vb = stg + 16384 + term * 8192;
                    #pragma unroll
                    for (int np = 0; np < 4; np++) {
                        int kvrow = pj * 16 + (lane & 15);
                        int dby   = np * 32 + ((lane >> 4) * 16);
                        uint32_t t4[4];
                        ldsm_x4_t(t4, vb + sw128((uint32_t)(kvrow * 128 + dby)));
                        vf[term][np * 2][0]     = t4[0];
                        vf[term][np * 2][1]     = t4[1];
                        vf[term][np * 2 + 1][0] = t4[2];
                        vf[term][np * 2 + 1][1] = t4[3];
                    }
                }
                #pragma unroll
                for (int nt = 0; nt < 8; nt++) {
                    mma_bf16(oacc[nt], ph, vf[0][nt]);
                    mma_bf16(oacc[nt], ph, vf[1][nt]);
                    mma_bf16(oacc[nt], pl, vf[0][nt]);
                }
            }
        }

        __syncthreads();   // all warps done with stage kt&1
        if (kt + 2 < NT) { load_kv(kt & 1, kt + 2); CP_COMMIT(); }
    }

    // ---- epilogue: normalize + split-write T ----
    const float inv0 = 1.0f / l0, inv1 = 1.0f / l1;
    const size_t rb0 = (size_t)(bofs + rowg) * DM + h * 64;
    const size_t rb1 = rb0 + (size_t)8 * DM;
    #pragma unroll
    for (int nt = 0; nt < 8; nt++) {
        int col = nt * 8 + t * 2;
        split_store_pair(oacc[nt][0] * inv0, oacc[nt][1] * inv0,
                         th + rb0 + col, tl + rb0 + col);
        split_store_pair(oacc[nt][2] * inv1, oacc[nt][3] * inv1,
                         th + rb1 + col, tl + rb1 + col);
    }
}

// ---------------------------------------------------------------------------
// Launcher
// ---------------------------------------------------------------------------
extern "C" void kernel_launch(void* const* d_in, const int* in_sizes, int n_in,
                              void* d_out, int out_size)
{
    const float* x   = (const float*)d_in[0];
    const float* W_q = (const float*)d_in[1];
    const float* W_k = (const float*)d_in[2];
    const float* W_v = (const float*)d_in[3];
    const float* W_o = (const float*)d_in[4];
    float* out = (float*)d_out;

    __nv_bfloat16 *xh, *xl, *Wh, *Wl, *qh, *ql, *kh, *kl, *vh, *vl, *th, *tl;
    cudaGetSymbolAddress((void**)&xh, g_xh);
    cudaGetSymbolAddress((void**)&xl, g_xl);
    cudaGetSymbolAddress((void**)&Wh, g_Wh);
    cudaGetSymbolAddress((void**)&Wl, g_Wl);
    cudaGetSymbolAddress((void**)&qh, g_qh);
    cudaGetSymbolAddress((void**)&ql, g_ql);
    cudaGetSymbolAddress((void**)&kh, g_kh);
    cudaGetSymbolAddress((void**)&kl, g_kl);
    cudaGetSymbolAddress((void**)&vh, g_vh);
    cudaGetSymbolAddress((void**)&vl, g_vl);
    cudaGetSymbolAddress((void**)&th, g_th);
    cudaGetSymbolAddress((void**)&tl, g_tl);

    cudaFuncSetAttribute(gemm_mma_split_kernel<true>,
                         cudaFuncAttributeMaxDynamicSharedMemorySize, GEMM_SMEM);
    cudaFuncSetAttribute(gemm_mma_split_kernel<false>,
                         cudaFuncAttributeMaxDynamicSharedMemorySize, GEMM_SMEM);
    cudaFuncSetAttribute(flash_attn_mma_kernel,
                         cudaFuncAttributeMaxDynamicSharedMemorySize, ATTN_SMEM);

    const int nx4 = (int)(NX / 4), nw4 = (int)(NW / 4);
    split_bf16_kernel<<<(nx4 + 255) / 256, 256>>>(x, xh, xl, nx4);
    split_bf16_kernel<<<(nw4 + 255) / 256, 256>>>(W_q, Wh + 0 * NW, Wl + 0 * NW, nw4);
    split_bf16_kernel<<<(nw4 + 255) / 256, 256>>>(W_k, Wh + 1 * NW, Wl + 1 * NW, nw4);
    split_bf16_kernel<<<(nw4 + 255) / 256, 256>>>(W_v, Wh + 2 * NW, Wl + 2 * NW, nw4);
    split_bf16_kernel<<<(nw4 + 255) / 256, 256>>>(W_o, Wh + 3 * NW, Wl + 3 * NW, nw4);

    dim3 gemm_grid(DM / 128, ROWS / 128);   // (8, 64)
    gemm_mma_split_kernel<true><<<gemm_grid, 256, GEMM_SMEM>>>(
        xh, xl, Wh + 0 * NW, Wl + 0 * NW, nullptr, qh, ql, ROWS, DM, DM);
    gemm_mma_split_kernel<true><<<gemm_grid, 256, GEMM_SMEM>>>(
        xh, xl, Wh + 1 * NW, Wl + 1 * NW, nullptr, kh, kl, ROWS, DM, DM);
    gemm_mma_split_kernel<true><<<gemm_grid, 256, GEMM_SMEM>>>(
        xh, xl, Wh + 2 * NW, Wl + 2 * NW, nullptr, vh, vl, ROWS, DM, DM);

    dim3 attn_grid(SEQ / 128, BATCH * NH);  // (16, 64)
    flash_attn_mma_kernel<<<attn_grid, 256, ATTN_SMEM>>>(qh, ql, kh, kl, vh, vl, th, tl);

    gemm_mma_split_kernel<false><<<gemm_grid, 256, GEMM_SMEM>>>(
        th, tl, Wh + 3 * NW, Wl + 3 * NW, out, nullptr, nullptr, ROWS, DM, DM);
}

// round 5
// speedup vs baseline: 3.7192x; 1.1735x over previous
#include <cuda_runtime.h>
#include <cuda_bf16.h>
#include <cstdint>

// Problem constants
static constexpr int BATCH = 4;
static constexpr int SEQ   = 2048;
static constexpr int DM    = 1024;
static constexpr int NH    = 16;
static constexpr int DH    = 64;
static constexpr int ROWS  = BATCH * SEQ;        // 8192
static constexpr size_t NX = (size_t)ROWS * DM;  // 8388608
static constexpr size_t NW = (size_t)DM * DM;    // 1048576

// Scratch (device globals: allocation-free)
__device__ __nv_bfloat16 g_xh[NX];
__device__ __nv_bfloat16 g_xl[NX];
__device__ __nv_bfloat16 g_Wh[4 * NW];   // Wq|Wk|Wv|Wo (QKV contiguous for fused GEMM)
__device__ __nv_bfloat16 g_Wl[4 * NW];
__device__ __nv_bfloat16 g_qkvh[3 * NX]; // Q|K|V hi
__device__ __nv_bfloat16 g_qkvl[3 * NX]; // Q|K|V lo
__device__ __nv_bfloat16 g_th[NX];
__device__ __nv_bfloat16 g_tl[NX];

// ---------------------------------------------------------------------------
// Helpers (non-'a'-gated: ldmatrix sm_75+, mma.sync bf16 sm_80+, cp.async sm_80+)
// ---------------------------------------------------------------------------
__device__ __forceinline__ uint32_t smem_u32(const void* p) {
    uint32_t a;
    asm("{ .reg .u64 t; cvta.to.shared.u64 t, %1; cvt.u32.u64 %0, t; }"
        : "=r"(a) : "l"(p));
    return a;
}
__device__ __forceinline__ uint32_t sw128(uint32_t off) {
    return off ^ ((off >> 3) & 0x70);
}
__device__ __forceinline__ void cp_async16(uint32_t saddr, const void* gaddr) {
    asm volatile("cp.async.cg.shared.global [%0], [%1], 16;"
                 :: "r"(saddr), "l"(gaddr));
}
#define CP_COMMIT() asm volatile("cp.async.commit_group;")
#define CP_WAIT(n)  asm volatile("cp.async.wait_group %0;" :: "n"(n))

__device__ __forceinline__ void ldsm_x4(uint32_t (&r)[4], uint32_t addr) {
    asm volatile("ldmatrix.sync.aligned.m8n8.x4.shared.b16 {%0,%1,%2,%3}, [%4];"
                 : "=r"(r[0]), "=r"(r[1]), "=r"(r[2]), "=r"(r[3]) : "r"(addr));
}
__device__ __forceinline__ void ldsm_x4_t(uint32_t (&r)[4], uint32_t addr) {
    asm volatile("ldmatrix.sync.aligned.m8n8.x4.trans.shared.b16 {%0,%1,%2,%3}, [%4];"
                 : "=r"(r[0]), "=r"(r[1]), "=r"(r[2]), "=r"(r[3]) : "r"(addr));
}
__device__ __forceinline__ void mma_bf16(float (&d)[4], const uint32_t (&a)[4],
                                         const uint32_t* b) {
    asm volatile(
        "mma.sync.aligned.m16n8k16.row.col.f32.bf16.bf16.f32 "
        "{%0,%1,%2,%3}, {%4,%5,%6,%7}, {%8,%9}, {%0,%1,%2,%3};"
        : "+f"(d[0]), "+f"(d[1]), "+f"(d[2]), "+f"(d[3])
        : "r"(a[0]), "r"(a[1]), "r"(a[2]), "r"(a[3]), "r"(b[0]), "r"(b[1]));
}

__device__ __forceinline__ void split_store_pair(float a, float b,
                                                 __nv_bfloat16* hp, __nv_bfloat16* lp) {
    __nv_bfloat162 h2 = __float22bfloat162_rn(make_float2(a, b));
    float2 hf = __bfloat1622float2(h2);
    __nv_bfloat162 l2 = __float22bfloat162_rn(make_float2(a - hf.x, b - hf.y));
    *reinterpret_cast<uint32_t*>(hp) = *reinterpret_cast<const uint32_t*>(&h2);
    *reinterpret_cast<uint32_t*>(lp) = *reinterpret_cast<const uint32_t*>(&l2);
}
__device__ __forceinline__ void pack_split(float a, float b, uint32_t& ph, uint32_t& pl) {
    __nv_bfloat162 h2 = __float22bfloat162_rn(make_float2(a, b));
    float2 hf = __bfloat1622float2(h2);
    __nv_bfloat162 l2 = __float22bfloat162_rn(make_float2(a - hf.x, b - hf.y));
    ph = *reinterpret_cast<const uint32_t*>(&h2);
    pl = *reinterpret_cast<const uint32_t*>(&l2);
}

// ---------------------------------------------------------------------------
// fp32 -> (hi, lo) bf16 split, vectorized by 4
// ---------------------------------------------------------------------------
__global__ __launch_bounds__(256) void split_bf16_kernel(
    const float* __restrict__ src, __nv_bfloat16* __restrict__ hi,
    __nv_bfloat16* __restrict__ lo, int n4)
{
    int i = blockIdx.x * blockDim.x + threadIdx.x;
    if (i >= n4) return;
    float4 v = reinterpret_cast<const float4*>(src)[i];
    __nv_bfloat162 h0 = __float22bfloat162_rn(make_float2(v.x, v.y));
    __nv_bfloat162 h1 = __float22bfloat162_rn(make_float2(v.z, v.w));
    float2 f0 = __bfloat1622float2(h0), f1 = __bfloat1622float2(h1);
    __nv_bfloat162 l0 = __float22bfloat162_rn(make_float2(v.x - f0.x, v.y - f0.y));
    __nv_bfloat162 l1 = __float22bfloat162_rn(make_float2(v.z - f1.x, v.w - f1.y));
    uint2 hv, lv;
    hv.x = *reinterpret_cast<uint32_t*>(&h0); hv.y = *reinterpret_cast<uint32_t*>(&h1);
    lv.x = *reinterpret_cast<uint32_t*>(&l0); lv.y = *reinterpret_cast<uint32_t*>(&l1);
    reinterpret_cast<uint2*>(hi)[i] = hv;
    reinterpret_cast<uint2*>(lo)[i] = lv;
}

// ---------------------------------------------------------------------------
// bf16-split GEMM (NT), K = 1024 fixed, all strides DM.
// C[row, col] = A[row,:] . B[col,:]   (B row index may span multiple weight mats)
// 128x128 CTA tile, BK=32, 4-stage cp.async ring, ONE sync per k-step.
// SPLIT_OUT: write (hi,lo) bf16 into per-matrix buffers (col>>10 selects matrix).
// ---------------------------------------------------------------------------
static constexpr int TILE_B    = 128 * 128;           // 16 KB (A or B, hi+lo packed)
static constexpr int STAGE_B   = 2 * TILE_B;          // 32 KB
static constexpr int GSTAGES   = 4;
static constexpr int GEMM_SMEM = GSTAGES * STAGE_B;   // 131072

template <bool SPLIT_OUT>
__global__ __launch_bounds__(256, 1) void gemm_mma_split_kernel(
    const __nv_bfloat16* __restrict__ Ah, const __nv_bfloat16* __restrict__ Al,
    const __nv_bfloat16* __restrict__ Bh, const __nv_bfloat16* __restrict__ Bl,
    float* __restrict__ C, __nv_bfloat16* __restrict__ Ch,
    __nv_bfloat16* __restrict__ Cl)
{
    extern __shared__ char smem[];
    const uint32_t sbase = smem_u32(smem);
    constexpr int K   = DM;
    constexpr int NKT = K / 32;          // 32 k-steps

    const int tid   = threadIdx.x;
    const int wid   = tid >> 5;
    const int lane  = tid & 31;
    const int warpm = wid >> 2;
    const int warpn = wid & 3;
    const int row0  = blockIdx.y * 128;
    const int col0  = blockIdx.x * 128;

    auto load_stage = [&](int s, int kt) {
        const uint32_t As = sbase + s * STAGE_B;
        const uint32_t Bs = As + TILE_B;
        const size_t kofs = (size_t)kt * 32;
        const __nv_bfloat16* Ah0 = Ah + (size_t)row0 * K + kofs;
        const __nv_bfloat16* Al0 = Al + (size_t)row0 * K + kofs;
        const __nv_bfloat16* Bh0 = Bh + (size_t)col0 * K + kofs;
        const __nv_bfloat16* Bl0 = Bl + (size_t)col0 * K + kofs;
        #pragma unroll
        for (int t = 0; t < 4; t++) {
            int v = t * 256 + tid;
            int r = v >> 3;
            int c = v & 7;                 // 0-3 hi chunks, 4-7 lo chunks
            uint32_t soff = sw128((uint32_t)(r * 128 + c * 16));
            cp_async16(As + soff, (c < 4 ? Ah0 : Al0) + (size_t)r * K + (c & 3) * 8);
            cp_async16(Bs + soff, (c < 4 ? Bh0 : Bl0) + (size_t)r * K + (c & 3) * 8);
        }
    };

    float acc[4][4][4];
    #pragma unroll
    for (int i = 0; i < 4; i++)
        #pragma unroll
        for (int j = 0; j < 4; j++)
            #pragma unroll
            for (int k = 0; k < 4; k++) acc[i][j][k] = 0.0f;

    load_stage(0, 0); CP_COMMIT();
    load_stage(1, 1); CP_COMMIT();
    load_stage(2, 2); CP_COMMIT();

    for (int kt = 0; kt < NKT; kt++) {
        CP_WAIT(2);
        __syncthreads();                  // single barrier per k-step

        const uint32_t As = sbase + (kt & 3) * STAGE_B;
        const uint32_t Bs = As + TILE_B;

        #pragma unroll
        for (int kc = 0; kc < 2; kc++) {
            const int jh = kc * 2;        // hi chunks
            const int jl = 4 + kc * 2;    // lo chunks

            // --- Ah, Bh fragments -> hh MMAs ---
            uint32_t Ahf[4][4], Bhf[4][2];
            #pragma unroll
            for (int mt = 0; mt < 4; mt++) {
                int row = warpm * 64 + mt * 16 + (lane & 15);
                ldsm_x4(Ahf[mt], As + sw128((uint32_t)(row * 128 + (jh + (lane >> 4)) * 16)));
            }
            #pragma unroll
            for (int p = 0; p < 2; p++) {
                int row = warpn * 32 + p * 16 + ((lane >> 4) << 3) + (lane & 7);
                uint32_t t4[4];
                ldsm_x4(t4, Bs + sw128((uint32_t)(row * 128 + (jh + ((lane >> 3) & 1)) * 16)));
                Bhf[p * 2][0]     = t4[0]; Bhf[p * 2][1]     = t4[1];
                Bhf[p * 2 + 1][0] = t4[2]; Bhf[p * 2 + 1][1] = t4[3];
            }
            #pragma unroll
            for (int mt = 0; mt < 4; mt++)
                #pragma unroll
                for (int nt = 0; nt < 4; nt++)
                    mma_bf16(acc[mt][nt], Ahf[mt], Bhf[nt]);

            // --- Bl fragments -> hl MMAs ---
            uint32_t Blf[4][2];
            #pragma unroll
            for (int p = 0; p < 2; p++) {
                int row = warpn * 32 + p * 16 + ((lane >> 4) << 3) + (lane & 7);
                uint32_t t4[4];
                ldsm_x4(t4, Bs + sw128((uint32_t)(row * 128 + (jl + ((lane >> 3) & 1)) * 16)));
                Blf[p * 2][0]     = t4[0]; Blf[p * 2][1]     = t4[1];
                Blf[p * 2 + 1][0] = t4[2]; Blf[p * 2 + 1][1] = t4[3];
            }
            #pragma unroll
            for (int mt = 0; mt < 4; mt++)
                #pragma unroll
                for (int nt = 0; nt < 4; nt++)
                    mma_bf16(acc[mt][nt], Ahf[mt], Blf[nt]);

            // --- Al fragments -> lh MMAs ---
            uint32_t Alf[4][4];
            #pragma unroll
            for (int mt = 0; mt < 4; mt++) {
                int row = warpm * 64 + mt * 16 + (lane & 15);
                ldsm_x4(Alf[mt], As + sw128((uint32_t)(row * 128 + (jl + (lane >> 4)) * 16)));
            }
            #pragma unroll
            for (int mt = 0; mt < 4; mt++)
                #pragma unroll
                for (int nt = 0; nt < 4; nt++)
                    mma_bf16(acc[mt][nt], Alf[mt], Bhf[nt]);
        }

        if (kt + 3 < NKT) load_stage((kt + 3) & 3, kt + 3);
        CP_COMMIT();                      // unconditional: uniform group counting
    }

    // ---- epilogue ----
    const int g = lane >> 2;
    const int t = lane & 3;
    if (SPLIT_OUT) {
        const int mat  = col0 >> 10;
        const int colb = col0 & 1023;
        __nv_bfloat16* ch = Ch + (size_t)mat * NX;
        __nv_bfloat16* cl = Cl + (size_t)mat * NX;
        #pragma unroll
        for (int mt = 0; mt < 4; mt++)
            #pragma unroll
            for (int nt = 0; nt < 4; nt++) {
                int row = row0 + warpm * 64 + mt * 16 + g;
                int col = colb + warpn * 32 + nt * 8 + t * 2;
                split_store_pair(acc[mt][nt][0], acc[mt][nt][1],
                                 ch + (size_t)row * DM + col, cl + (size_t)row * DM + col);
                split_store_pair(acc[mt][nt][2], acc[mt][nt][3],
                                 ch + (size_t)(row + 8) * DM + col,
                                 cl + (size_t)(row + 8) * DM + col);
            }
    } else {
        #pragma unroll
        for (int mt = 0; mt < 4; mt++)
            #pragma unroll
            for (int nt = 0; nt < 4; nt++) {
                int row = row0 + warpm * 64 + mt * 16 + g;
                int col = col0 + warpn * 32 + nt * 8 + t * 2;
                float2 v0 = make_float2(acc[mt][nt][0], acc[mt][nt][1]);
                float2 v1 = make_float2(acc[mt][nt][2], acc[mt][nt][3]);
                *reinterpret_cast<float2*>(&C[(size_t)row * DM + col])       = v0;
                *reinterpret_cast<float2*>(&C[(size_t)(row + 8) * DM + col]) = v1;
            }
    }
}

// ---------------------------------------------------------------------------
// Tensor-core flash attention (split-bf16, causal) — unchanged from R4.
// One CTA = 128 query rows of one (b,h). 8 warps x 16 rows. KV tiles of 64,
// double-buffered cp.async. SMEM: Q 32KB + 2 x 32KB = 96KB.
// ---------------------------------------------------------------------------
static constexpr int ATTN_SMEM = 32768 + 2 * 32768;

__global__ __launch_bounds__(256, 1) void flash_attn_mma_kernel(
    const __nv_bfloat16* __restrict__ qh, const __nv_bfloat16* __restrict__ ql,
    const __nv_bfloat16* __restrict__ kh, const __nv_bfloat16* __restrict__ kl,
    const __nv_bfloat16* __restrict__ vh, const __nv_bfloat16* __restrict__ vl,
    __nv_bfloat16* __restrict__ th, __nv_bfloat16* __restrict__ tl)
{
    extern __shared__ char smem[];
    const uint32_t sbase = smem_u32(smem);

    const int tid  = threadIdx.x;
    const int wid  = tid >> 5;
    const int lane = tid & 31;
    const int g    = lane >> 2;
    const int t    = lane & 3;

    const int qb = (SEQ / 128 - 1) - blockIdx.x;
    const int bh = blockIdx.y;
    const int b  = bh >> 4;
    const int h  = bh & 15;
    const int q0 = qb * 128;
    const int bofs = b * SEQ;
    const int NT = 2 * qb + 2;
    const int rowg = q0 + wid * 16 + g;

    auto load_q = [&]() {
        #pragma unroll
        for (int term = 0; term < 2; term++) {
            const __nv_bfloat16* src = term ? ql : qh;
            #pragma unroll
            for (int tt = 0; tt < 4; tt++) {
                int v = tt * 256 + tid;
                int r = v >> 3;
                int c = v & 7;
                cp_async16(sbase + term * 16384 + sw128((uint32_t)(r * 128 + c * 16)),
                           src + (size_t)(bofs + q0 + r) * DM + h * 64 + c * 8);
            }
        }
    };
    auto load_kv = [&](int stage, int kt2) {
        const int kv = kt2 * 64;
        const uint32_t base = sbase + 32768 + stage * 32768;
        const __nv_bfloat16* bufs[4] = {kh, kl, vh, vl};
        #pragma unroll
        for (int buf = 0; buf < 4; buf++) {
            #pragma unroll
            for (int tt = 0; tt < 2; tt++) {
                int v = tt * 256 + tid;
                int r = v >> 3;
                int c = v & 7;
                cp_async16(base + buf * 8192 + sw128((uint32_t)(r * 128 + c * 16)),
                           bufs[buf] + (size_t)(bofs + kv + r) * DM + h * 64 + c * 8);
            }
        }
    };

    load_q();
    load_kv(0, 0); CP_COMMIT();
    load_kv(1, 1); CP_COMMIT();
    CP_WAIT(1);
    __syncthreads();

    uint32_t qf[2][4][4];
    #pragma unroll
    for (int term = 0; term < 2; term++) {
        const uint32_t qbse = sbase + term * 16384;
        #pragma unroll
        for (int j = 0; j < 4; j++) {
            int row   = wid * 16 + (lane & 15);
            int chunk = j * 2 + (lane >> 4);
            ldsm_x4(qf[term][j], qbse + sw128((uint32_t)(row * 128 + chunk * 16)));
        }
    }

    float m0 = -1e30f, m1 = -1e30f, l0 = 0.0f, l1 = 0.0f;
    float oacc[8][4];
    #pragma unroll
    for (int nt = 0; nt < 8; nt++)
        #pragma unroll
        for (int c = 0; c < 4; c++) oacc[nt][c] = 0.0f;

    for (int kt = 0; kt < NT; kt++) {
        if (kt + 1 < NT) { CP_WAIT(1); } else { CP_WAIT(0); }
        __syncthreads();

        const int kv0 = kt * 64;
        const bool active = kv0 <= q0 + wid * 16 + 15;
        if (active) {
            const uint32_t stg = sbase + 32768 + (kt & 1) * 32768;

            float sacc[8][4];
            #pragma unroll
            for (int nt = 0; nt < 8; nt++)
                #pragma unroll
                for (int c = 0; c < 4; c++) sacc[nt][c] = 0.0f;

            #pragma unroll
            for (int j = 0; j < 4; j++) {
                uint32_t kf[2][8][2];
                #pragma unroll
                for (int term = 0; term < 2; term++) {
                    const uint32_t kb = stg + term * 8192;
                    #pragma unroll
                    for (int np = 0; np < 4; np++) {
                        int row   = np * 16 + ((lane >> 4) << 3) + (lane & 7);
                        int chunk = j * 2 + ((lane >> 3) & 1);
                        uint32_t t4[4];
                        ldsm_x4(t4, kb + sw128((uint32_t)(row * 128 + chunk * 16)));
                        kf[term][np * 2][0]     = t4[0];
                        kf[term][np * 2][1]     = t4[1];
                        kf[term][np * 2 + 1][0] = t4[2];
                        kf[term][np * 2 + 1][1] = t4[3];
                    }
                }
                #pragma unroll
                for (int nt = 0; nt < 8; nt++) {
                    mma_bf16(sacc[nt], qf[0][j], kf[0][nt]);
                    mma_bf16(sacc[nt], qf[0][j], kf[1][nt]);
                    mma_bf16(sacc[nt], qf[1][j], kf[0][nt]);
                }
            }

            const bool domask = (kv0 + 63) > (q0 + wid * 16);
            #pragma unroll
            for (int nt = 0; nt < 8; nt++) {
                #pragma unroll
                for (int c = 0; c < 4; c++) {
                    float s = sacc[nt][c] * 0.125f;
                    if (domask) {
                        int col = kv0 + nt * 8 + t * 2 + (c & 1);
                        int row = (c < 2) ? rowg : rowg + 8;
                        if (col > row) s = -1e30f;
                    }
                    sacc[nt][c] = s;
                }
            }

            float mx0 = -1e30f, mx1 = -1e30f;
            #pragma unroll
            for (int nt = 0; nt < 8; nt++) {
                mx0 = fmaxf(mx0, fmaxf(sacc[nt][0], sacc[nt][1]));
                mx1 = fmaxf(mx1, fmaxf(sacc[nt][2], sacc[nt][3]));
            }
            mx0 = fmaxf(mx0, __shfl_xor_sync(0xffffffffu, mx0, 1));
            mx0 = fmaxf(mx0, __shfl_xor_sync(0xffffffffu, mx0, 2));
            mx1 = fmaxf(mx1, __shfl_xor_sync(0xffffffffu, mx1, 1));
            mx1 = fmaxf(mx1, __shfl_xor_sync(0xffffffffu, mx1, 2));
            float mnew0 = fmaxf(m0, mx0), mnew1 = fmaxf(m1, mx1);
            float a0 = __expf(m0 - mnew0), a1 = __expf(m1 - mnew1);
            m0 = mnew0; m1 = mnew1;

            float rs0 = 0.0f, rs1 = 0.0f;
            #pragma unroll
            for (int nt = 0; nt < 8; nt++) {
                float p0 = __expf(sacc[nt][0] - mnew0);
                float p1 = __expf(sacc[nt][1] - mnew0);
                float p2 = __expf(sacc[nt][2] - mnew1);
                float p3 = __expf(sacc[nt][3] - mnew1);
                sacc[nt][0] = p0; sacc[nt][1] = p1;
                sacc[nt][2] = p2; sacc[nt][3] = p3;
                rs0 += p0 + p1; rs1 += p2 + p3;
            }
            rs0 += __shfl_xor_sync(0xffffffffu, rs0, 1);
            rs0 += __shfl_xor_sync(0xffffffffu, rs0, 2);
            rs1 += __shfl_xor_sync(0xffffffffu, rs1, 1);
            rs1 += __shfl_xor_sync(0xffffffffu, rs1, 2);
            l0 = l0 * a0 + rs0;
            l1 = l1 * a1 + rs1;
            #pragma unroll
            for (int nt = 0; nt < 8; nt++) {
                oacc[nt][0] *= a0; oacc[nt][1] *= a0;
                oacc[nt][2] *= a1; oacc[nt][3] *= a1;
            }

            #pragma unroll
            for (int pj = 0; pj < 4; pj++) {
                const float* se = sacc[2 * pj];
                const float* so = sacc[2 * pj + 1];
                uint32_t ph[4], pl[4];
                pack_split(se[0], se[1], ph[0], pl[0]);
                pack_split(se[2], se[3], ph[1], pl[1]);
                pack_split(so[0], so[1], ph[2], pl[2]);
                pack_split(so[2], so[3], ph[3], pl[3]);

                uint32_t vf[2][8][2];
                #pragma unroll
                for (int term = 0; term < 2; term++) {
                    const uint32_t vb = stg + 16384 + term * 8192;
                    #pragma unroll
                    for (int np = 0; np < 4; np++) {
                        int kvrow = pj * 16 + (lane & 15);
                        int dby   = np * 32 + ((lane >> 4) * 16);
                        uint32_t t4[4];
                        ldsm_x4_t(t4, vb + sw128((uint32_t)(kvrow * 128 + dby)));
                        vf[term][np * 2][0]     = t4[0];
                        vf[term][np * 2][1]     = t4[1];
                        vf[term][np * 2 + 1][0] = t4[2];
                        vf[term][np * 2 + 1][1] = t4[3];
                    }
                }
                #pragma unroll
                for (int nt = 0; nt < 8; nt++) {
                    mma_bf16(oacc[nt], ph, vf[0][nt]);
                    mma_bf16(oacc[nt], ph, vf[1][nt]);
                    mma_bf16(oacc[nt], pl, vf[0][nt]);
                }
            }
        }

        __syncthreads();
        if (kt + 2 < NT) { load_kv(kt & 1, kt + 2); CP_COMMIT(); }
    }

    const float inv0 = 1.0f / l0, inv1 = 1.0f / l1;
    const size_t rb0 = (size_t)(bofs + rowg) * DM + h * 64;
    const size_t rb1 = rb0 + (size_t)8 * DM;
    #pragma unroll
    for (int nt = 0; nt < 8; nt++) {
        int col = nt * 8 + t * 2;
        split_store_pair(oacc[nt][0] * inv0, oacc[nt][1] * inv0,
                         th + rb0 + col, tl + rb0 + col);
        split_store_pair(oacc[nt][2] * inv1, oacc[nt][3] * inv1,
                         th + rb1 + col, tl + rb1 + col);
    }
}

// ---------------------------------------------------------------------------
// Launcher
// ---------------------------------------------------------------------------
extern "C" void kernel_launch(void* const* d_in, const int* in_sizes, int n_in,
                              void* d_out, int out_size)
{
    const float* x   = (const float*)d_in[0];
    const float* W_q = (const float*)d_in[1];
    const float* W_k = (const float*)d_in[2];
    const float* W_v = (const float*)d_in[3];
    const float* W_o = (const float*)d_in[4];
    float* out = (float*)d_out;

    __nv_bfloat16 *xh, *xl, *Wh, *Wl, *qkvh, *qkvl, *th, *tl;
    cudaGetSymbolAddress((void**)&xh, g_xh);
    cudaGetSymbolAddress((void**)&xl, g_xl);
    cudaGetSymbolAddress((void**)&Wh, g_Wh);
    cudaGetSymbolAddress((void**)&Wl, g_Wl);
    cudaGetSymbolAddress((void**)&qkvh, g_qkvh);
    cudaGetSymbolAddress((void**)&qkvl, g_qkvl);
    cudaGetSymbolAddress((void**)&th, g_th);
    cudaGetSymbolAddress((void**)&tl, g_tl);

    cudaFuncSetAttribute(gemm_mma_split_kernel<true>,
                         cudaFuncAttributeMaxDynamicSharedMemorySize, GEMM_SMEM);
    cudaFuncSetAttribute(gemm_mma_split_kernel<false>,
                         cudaFuncAttributeMaxDynamicSharedMemorySize, GEMM_SMEM);
    cudaFuncSetAttribute(flash_attn_mma_kernel,
                         cudaFuncAttributeMaxDynamicSharedMemorySize, ATTN_SMEM);

    const int nx4 = (int)(NX / 4), nw4 = (int)(NW / 4);
    split_bf16_kernel<<<(nx4 + 255) / 256, 256>>>(x, xh, xl, nx4);
    split_bf16_kernel<<<(nw4 + 255) / 256, 256>>>(W_q, Wh + 0 * NW, Wl + 0 * NW, nw4);
    split_bf16_kernel<<<(nw4 + 255) / 256, 256>>>(W_k, Wh + 1 * NW, Wl + 1 * NW, nw4);
    split_bf16_kernel<<<(nw4 + 255) / 256, 256>>>(W_v, Wh + 2 * NW, Wl + 2 * NW, nw4);
    split_bf16_kernel<<<(nw4 + 255) / 256, 256>>>(W_o, Wh + 3 * NW, Wl + 3 * NW, nw4);

    // Fused QKV GEMM: N = 3072 across Wq|Wk|Wv, outputs into per-matrix buffers
    dim3 qkv_grid(3 * DM / 128, ROWS / 128);   // (24, 64)
    gemm_mma_split_kernel<true><<<qkv_grid, 256, GEMM_SMEM>>>(
        xh, xl, Wh, Wl, nullptr, qkvh, qkvl);

    dim3 attn_grid(SEQ / 128, BATCH * NH);     // (16, 64)
    flash_attn_mma_kernel<<<attn_grid, 256, ATTN_SMEM>>>(
        qkvh, qkvl, qkvh + NX, qkvl + NX, qkvh + 2 * NX, qkvl + 2 * NX, th, tl);

    dim3 o_grid(DM / 128, ROWS / 128);         // (8, 64)
    gemm_mma_split_kernel<false><<<o_grid, 256, GEMM_SMEM>>>(
        th, tl, Wh + 3 * NW, Wl + 3 * NW, out, nullptr, nullptr);
}

// round 6
// speedup vs baseline: 3.7508x; 1.0085x over previous
#include <cuda_runtime.h>
#include <cuda_bf16.h>
#include <cstdint>

// Problem constants
static constexpr int BATCH = 4;
static constexpr int SEQ   = 2048;
static constexpr int DM    = 1024;
static constexpr int NH    = 16;
static constexpr int DH    = 64;
static constexpr int ROWS  = BATCH * SEQ;        // 8192
static constexpr size_t NX = (size_t)ROWS * DM;  // 8388608
static constexpr size_t NW = (size_t)DM * DM;    // 1048576

// Scratch (device globals: allocation-free)
__device__ __nv_bfloat16 g_xh[NX];
__device__ __nv_bfloat16 g_xl[NX];
__device__ __nv_bfloat16 g_Wh[4 * NW];   // Wq|Wk|Wv|Wo
__device__ __nv_bfloat16 g_Wl[4 * NW];
__device__ __nv_bfloat16 g_qkvh[3 * NX]; // Q|K|V hi
__device__ __nv_bfloat16 g_qkvl[3 * NX]; // Q|K|V lo
__device__ __nv_bfloat16 g_th[NX];
__device__ __nv_bfloat16 g_tl[NX];

// ---------------------------------------------------------------------------
// Helpers
// ---------------------------------------------------------------------------
__device__ __forceinline__ uint32_t smem_u32(const void* p) {
    uint32_t a;
    asm("{ .reg .u64 t; cvta.to.shared.u64 t, %1; cvt.u32.u64 %0, t; }"
        : "=r"(a) : "l"(p));
    return a;
}
__device__ __forceinline__ uint32_t sw128(uint32_t off) {
    return off ^ ((off >> 3) & 0x70);
}
__device__ __forceinline__ void cp_async16(uint32_t saddr, const void* gaddr) {
    asm volatile("cp.async.cg.shared.global [%0], [%1], 16;"
                 :: "r"(saddr), "l"(gaddr));
}
#define CP_COMMIT() asm volatile("cp.async.commit_group;")
#define CP_WAIT(n)  asm volatile("cp.async.wait_group %0;" :: "n"(n))

__device__ __forceinline__ void ldsm_x4(uint32_t (&r)[4], uint32_t addr) {
    asm volatile("ldmatrix.sync.aligned.m8n8.x4.shared.b16 {%0,%1,%2,%3}, [%4];"
                 : "=r"(r[0]), "=r"(r[1]), "=r"(r[2]), "=r"(r[3]) : "r"(addr));
}
__device__ __forceinline__ void ldsm_x4_t(uint32_t (&r)[4], uint32_t addr) {
    asm volatile("ldmatrix.sync.aligned.m8n8.x4.trans.shared.b16 {%0,%1,%2,%3}, [%4];"
                 : "=r"(r[0]), "=r"(r[1]), "=r"(r[2]), "=r"(r[3]) : "r"(addr));
}
__device__ __forceinline__ void mma_bf16(float (&d)[4], const uint32_t (&a)[4],
                                         const uint32_t* b) {
    asm volatile(
        "mma.sync.aligned.m16n8k16.row.col.f32.bf16.bf16.f32 "
        "{%0,%1,%2,%3}, {%4,%5,%6,%7}, {%8,%9}, {%0,%1,%2,%3};"
        : "+f"(d[0]), "+f"(d[1]), "+f"(d[2]), "+f"(d[3])
        : "r"(a[0]), "r"(a[1]), "r"(a[2]), "r"(a[3]), "r"(b[0]), "r"(b[1]));
}

__device__ __forceinline__ void split_store_pair(float a, float b,
                                                 __nv_bfloat16* hp, __nv_bfloat16* lp) {
    __nv_bfloat162 h2 = __float22bfloat162_rn(make_float2(a, b));
    float2 hf = __bfloat1622float2(h2);
    __nv_bfloat162 l2 = __float22bfloat162_rn(make_float2(a - hf.x, b - hf.y));
    *reinterpret_cast<uint32_t*>(hp) = *reinterpret_cast<const uint32_t*>(&h2);
    *reinterpret_cast<uint32_t*>(lp) = *reinterpret_cast<const uint32_t*>(&l2);
}
__device__ __forceinline__ void pack_split(float a, float b, uint32_t& ph, uint32_t& pl) {
    __nv_bfloat162 h2 = __float22bfloat162_rn(make_float2(a, b));
    float2 hf = __bfloat1622float2(h2);
    __nv_bfloat162 l2 = __float22bfloat162_rn(make_float2(a - hf.x, b - hf.y));
    ph = *reinterpret_cast<const uint32_t*>(&h2);
    pl = *reinterpret_cast<const uint32_t*>(&l2);
}

// ---------------------------------------------------------------------------
// fp32 -> (hi, lo) bf16 split
// ---------------------------------------------------------------------------
__global__ __launch_bounds__(256) void split_bf16_kernel(
    const float* __restrict__ src, __nv_bfloat16* __restrict__ hi,
    __nv_bfloat16* __restrict__ lo, int n4)
{
    int i = blockIdx.x * blockDim.x + threadIdx.x;
    if (i >= n4) return;
    float4 v = reinterpret_cast<const float4*>(src)[i];
    __nv_bfloat162 h0 = __float22bfloat162_rn(make_float2(v.x, v.y));
    __nv_bfloat162 h1 = __float22bfloat162_rn(make_float2(v.z, v.w));
    float2 f0 = __bfloat1622float2(h0), f1 = __bfloat1622float2(h1);
    __nv_bfloat162 l0 = __float22bfloat162_rn(make_float2(v.x - f0.x, v.y - f0.y));
    __nv_bfloat162 l1 = __float22bfloat162_rn(make_float2(v.z - f1.x, v.w - f1.y));
    uint2 hv, lv;
    hv.x = *reinterpret_cast<uint32_t*>(&h0); hv.y = *reinterpret_cast<uint32_t*>(&h1);
    lv.x = *reinterpret_cast<uint32_t*>(&l0); lv.y = *reinterpret_cast<uint32_t*>(&l1);
    reinterpret_cast<uint2*>(hi)[i] = hv;
    reinterpret_cast<uint2*>(lo)[i] = lv;
}

// ---------------------------------------------------------------------------
// bf16-split GEMM (NT), K = 1024 fixed (unchanged from R5 — proven)
// ---------------------------------------------------------------------------
static constexpr int TILE_B    = 128 * 128;
static constexpr int STAGE_B   = 2 * TILE_B;
static constexpr int GSTAGES   = 4;
static constexpr int GEMM_SMEM = GSTAGES * STAGE_B;   // 131072

template <bool SPLIT_OUT>
__global__ __launch_bounds__(256, 1) void gemm_mma_split_kernel(
    const __nv_bfloat16* __restrict__ Ah, const __nv_bfloat16* __restrict__ Al,
    const __nv_bfloat16* __restrict__ Bh, const __nv_bfloat16* __restrict__ Bl,
    float* __restrict__ C, __nv_bfloat16* __restrict__ Ch,
    __nv_bfloat16* __restrict__ Cl)
{
    extern __shared__ char smem[];
    const uint32_t sbase = smem_u32(smem);
    constexpr int K   = DM;
    constexpr int NKT = K / 32;

    const int tid   = threadIdx.x;
    const int wid   = tid >> 5;
    const int lane  = tid & 31;
    const int warpm = wid >> 2;
    const int warpn = wid & 3;
    const int row0  = blockIdx.y * 128;
    const int col0  = blockIdx.x * 128;

    auto load_stage = [&](int s, int kt) {
        const uint32_t As = sbase + s * STAGE_B;
        const uint32_t Bs = As + TILE_B;
        const size_t kofs = (size_t)kt * 32;
        const __nv_bfloat16* Ah0 = Ah + (size_t)row0 * K + kofs;
        const __nv_bfloat16* Al0 = Al + (size_t)row0 * K + kofs;
        const __nv_bfloat16* Bh0 = Bh + (size_t)col0 * K + kofs;
        const __nv_bfloat16* Bl0 = Bl + (size_t)col0 * K + kofs;
        #pragma unroll
        for (int t = 0; t < 4; t++) {
            int v = t * 256 + tid;
            int r = v >> 3;
            int c = v & 7;
            uint32_t soff = sw128((uint32_t)(r * 128 + c * 16));
            cp_async16(As + soff, (c < 4 ? Ah0 : Al0) + (size_t)r * K + (c & 3) * 8);
            cp_async16(Bs + soff, (c < 4 ? Bh0 : Bl0) + (size_t)r * K + (c & 3) * 8);
        }
    };

    float acc[4][4][4];
    #pragma unroll
    for (int i = 0; i < 4; i++)
        #pragma unroll
        for (int j = 0; j < 4; j++)
            #pragma unroll
            for (int k = 0; k < 4; k++) acc[i][j][k] = 0.0f;

    load_stage(0, 0); CP_COMMIT();
    load_stage(1, 1); CP_COMMIT();
    load_stage(2, 2); CP_COMMIT();

    for (int kt = 0; kt < NKT; kt++) {
        CP_WAIT(2);
        __syncthreads();

        const uint32_t As = sbase + (kt & 3) * STAGE_B;
        const uint32_t Bs = As + TILE_B;

        #pragma unroll
        for (int kc = 0; kc < 2; kc++) {
            const int jh = kc * 2;
            const int jl = 4 + kc * 2;

            uint32_t Ahf[4][4], Bhf[4][2];
            #pragma unroll
            for (int mt = 0; mt < 4; mt++) {
                int row = warpm * 64 + mt * 16 + (lane & 15);
                ldsm_x4(Ahf[mt], As + sw128((uint32_t)(row * 128 + (jh + (lane >> 4)) * 16)));
            }
            #pragma unroll
            for (int p = 0; p < 2; p++) {
                int row = warpn * 32 + p * 16 + ((lane >> 4) << 3) + (lane & 7);
                uint32_t t4[4];
                ldsm_x4(t4, Bs + sw128((uint32_t)(row * 128 + (jh + ((lane >> 3) & 1)) * 16)));
                Bhf[p * 2][0]     = t4[0]; Bhf[p * 2][1]     = t4[1];
                Bhf[p * 2 + 1][0] = t4[2]; Bhf[p * 2 + 1][1] = t4[3];
            }
            #pragma unroll
            for (int mt = 0; mt < 4; mt++)
                #pragma unroll
                for (int nt = 0; nt < 4; nt++)
                    mma_bf16(acc[mt][nt], Ahf[mt], Bhf[nt]);

            uint32_t Blf[4][2];
            #pragma unroll
            for (int p = 0; p < 2; p++) {
                int row = warpn * 32 + p * 16 + ((lane >> 4) << 3) + (lane & 7);
                uint32_t t4[4];
                ldsm_x4(t4, Bs + sw128((uint32_t)(row * 128 + (jl + ((lane >> 3) & 1)) * 16)));
                Blf[p * 2][0]     = t4[0]; Blf[p * 2][1]     = t4[1];
                Blf[p * 2 + 1][0] = t4[2]; Blf[p * 2 + 1][1] = t4[3];
            }
            #pragma unroll
            for (int mt = 0; mt < 4; mt++)
                #pragma unroll
                for (int nt = 0; nt < 4; nt++)
                    mma_bf16(acc[mt][nt], Ahf[mt], Blf[nt]);

            uint32_t Alf[4][4];
            #pragma unroll
            for (int mt = 0; mt < 4; mt++) {
                int row = warpm * 64 + mt * 16 + (lane & 15);
                ldsm_x4(Alf[mt], As + sw128((uint32_t)(row * 128 + (jl + (lane >> 4)) * 16)));
            }
            #pragma unroll
            for (int mt = 0; mt < 4; mt++)
                #pragma unroll
                for (int nt = 0; nt < 4; nt++)
                    mma_bf16(acc[mt][nt], Alf[mt], Bhf[nt]);
        }

        if (kt + 3 < NKT) load_stage((kt + 3) & 3, kt + 3);
        CP_COMMIT();
    }

    const int g = lane >> 2;
    const int t = lane & 3;
    if (SPLIT_OUT) {
        const int mat  = col0 >> 10;
        const int colb = col0 & 1023;
        __nv_bfloat16* ch = Ch + (size_t)mat * NX;
        __nv_bfloat16* cl = Cl + (size_t)mat * NX;
        #pragma unroll
        for (int mt = 0; mt < 4; mt++)
            #pragma unroll
            for (int nt = 0; nt < 4; nt++) {
                int row = row0 + warpm * 64 + mt * 16 + g;
                int col = colb + warpn * 32 + nt * 8 + t * 2;
                split_store_pair(acc[mt][nt][0], acc[mt][nt][1],
                                 ch + (size_t)row * DM + col, cl + (size_t)row * DM + col);
                split_store_pair(acc[mt][nt][2], acc[mt][nt][3],
                                 ch + (size_t)(row + 8) * DM + col,
                                 cl + (size_t)(row + 8) * DM + col);
            }
    } else {
        #pragma unroll
        for (int mt = 0; mt < 4; mt++)
            #pragma unroll
            for (int nt = 0; nt < 4; nt++) {
                int row = row0 + warpm * 64 + mt * 16 + g;
                int col = col0 + warpn * 32 + nt * 8 + t * 2;
                float2 v0 = make_float2(acc[mt][nt][0], acc[mt][nt][1]);
                float2 v1 = make_float2(acc[mt][nt][2], acc[mt][nt][3]);
                *reinterpret_cast<float2*>(&C[(size_t)row * DM + col])       = v0;
                *reinterpret_cast<float2*>(&C[(size_t)(row + 8) * DM + col]) = v1;
            }
    }
}

// ---------------------------------------------------------------------------
// Tensor-core flash attention (split-bf16, causal), BN=128 KV tiles.
// One CTA = 128 query rows of one (b,h). 8 warps x 16 rows. NT = qb+1 tiles.
// log2-domain softmax (exp2f). Mask only on the diagonal (last) tile.
// SMEM: Q 32KB + 2 stages x 64KB (Kh|Kl|Vh|Vl, 16KB each) = 160KB.
// ---------------------------------------------------------------------------
static constexpr int ATTN_SMEM = 32768 + 2 * 65536;   // 163840
static constexpr float SCALE_L2E = 0.125f * 1.4426950408889634f;

__global__ __launch_bounds__(256, 1) void flash_attn_mma_kernel(
    const __nv_bfloat16* __restrict__ qh, const __nv_bfloat16* __restrict__ ql,
    const __nv_bfloat16* __restrict__ kh, const __nv_bfloat16* __restrict__ kl,
    const __nv_bfloat16* __restrict__ vh, const __nv_bfloat16* __restrict__ vl,
    __nv_bfloat16* __restrict__ th, __nv_bfloat16* __restrict__ tl)
{
    extern __shared__ char smem[];
    const uint32_t sbase = smem_u32(smem);

    const int tid  = threadIdx.x;
    const int wid  = tid >> 5;
    const int lane = tid & 31;
    const int g    = lane >> 2;
    const int t    = lane & 3;

    const int qb = (SEQ / 128 - 1) - blockIdx.x;   // heavy blocks first
    const int bh = blockIdx.y;
    const int b  = bh >> 4;
    const int h  = bh & 15;
    const int q0 = qb * 128;
    const int bofs = b * SEQ;
    const int NT = qb + 1;                          // kv tiles of 128
    const int rowg = q0 + wid * 16 + g;

    auto load_q = [&]() {
        #pragma unroll
        for (int term = 0; term < 2; term++) {
            const __nv_bfloat16* src = term ? ql : qh;
            #pragma unroll
            for (int tt = 0; tt < 4; tt++) {
                int v = tt * 256 + tid;
                int r = v >> 3;
                int c = v & 7;
                cp_async16(sbase + term * 16384 + sw128((uint32_t)(r * 128 + c * 16)),
                           src + (size_t)(bofs + q0 + r) * DM + h * 64 + c * 8);
            }
        }
    };
    auto load_kv = [&](int stage, int kt2) {
        const int kv = kt2 * 128;
        const uint32_t base = sbase + 32768 + stage * 65536;
        const __nv_bfloat16* bufs[4] = {kh, kl, vh, vl};
        #pragma unroll
        for (int buf = 0; buf < 4; buf++) {
            #pragma unroll
            for (int tt = 0; tt < 4; tt++) {
                int v = tt * 256 + tid;
                int r = v >> 3;          // 0..127
                int c = v & 7;
                cp_async16(base + buf * 16384 + sw128((uint32_t)(r * 128 + c * 16)),
                           bufs[buf] + (size_t)(bofs + kv + r) * DM + h * 64 + c * 8);
            }
        }
    };

    load_q();
    load_kv(0, 0); CP_COMMIT();
    load_kv(1, NT > 1 ? 1 : 0); CP_COMMIT();
    CP_WAIT(1);
    __syncthreads();

    // Q fragments persistent: [term][j][4]
    uint32_t qf[2][4][4];
    #pragma unroll
    for (int term = 0; term < 2; term++) {
        const uint32_t qbse = sbase + term * 16384;
        #pragma unroll
        for (int j = 0; j < 4; j++) {
            int row   = wid * 16 + (lane & 15);
            int chunk = j * 2 + (lane >> 4);
            ldsm_x4(qf[term][j], qbse + sw128((uint32_t)(row * 128 + chunk * 16)));
        }
    }

    float m0 = -1e30f, m1 = -1e30f, l0 = 0.0f, l1 = 0.0f;
    float oacc[8][4];
    #pragma unroll
    for (int nt = 0; nt < 8; nt++)
        #pragma unroll
        for (int c = 0; c < 4; c++) oacc[nt][c] = 0.0f;

    for (int kt = 0; kt < NT; kt++) {
        if (kt + 1 < NT) { CP_WAIT(1); } else { CP_WAIT(0); }
        __syncthreads();

        const int kv0 = kt * 128;
        const uint32_t stg = sbase + 32768 + (kt & 1) * 65536;

        // ---- S = (Qh+Ql) @ (Kh+Kl)^T over 128 cols (two n-halves) ----
        float sacc[16][4];
        #pragma unroll
        for (int nt = 0; nt < 16; nt++)
            #pragma unroll
            for (int c = 0; c < 4; c++) sacc[nt][c] = 0.0f;

        #pragma unroll
        for (int half = 0; half < 2; half++) {
            #pragma unroll
            for (int j = 0; j < 4; j++) {
                uint32_t kf[2][8][2];
                #pragma unroll
                for (int term = 0; term < 2; term++) {
                    const uint32_t kb = stg + term * 16384;
                    #pragma unroll
                    for (int np = 0; np < 4; np++) {
                        int row   = half * 64 + np * 16 + ((lane >> 4) << 3) + (lane & 7);
                        int chunk = j * 2 + ((lane >> 3) & 1);
                        uint32_t t4[4];
                        ldsm_x4(t4, kb + sw128((uint32_t)(row * 128 + chunk * 16)));
                        kf[term][np * 2][0]     = t4[0];
                        kf[term][np * 2][1]     = t4[1];
                        kf[term][np * 2 + 1][0] = t4[2];
                        kf[term][np * 2 + 1][1] = t4[3];
                    }
                }
                #pragma unroll
                for (int nt = 0; nt < 8; nt++) {
                    mma_bf16(sacc[half * 8 + nt], qf[0][j], kf[0][nt]);
                    mma_bf16(sacc[half * 8 + nt], qf[0][j], kf[1][nt]);
                    mma_bf16(sacc[half * 8 + nt], qf[1][j], kf[0][nt]);
                }
            }
        }

        // ---- scale to log2 domain + causal mask (diagonal tile only) ----
        const bool lastt = (kt == NT - 1);
        #pragma unroll
        for (int nt = 0; nt < 16; nt++) {
            #pragma unroll
            for (int c = 0; c < 4; c++) {
                float s = sacc[nt][c] * SCALE_L2E;
                if (lastt) {
                    int col = kv0 + nt * 8 + t * 2 + (c & 1);
                    int row = (c < 2) ? rowg : rowg + 8;
                    if (col > row) s = -1e30f;
                }
                sacc[nt][c] = s;
            }
        }

        // ---- online softmax (base-2) ----
        float mx0 = -1e30f, mx1 = -1e30f;
        #pragma unroll
        for (int nt = 0; nt < 16; nt++) {
            mx0 = fmaxf(mx0, fmaxf(sacc[nt][0], sacc[nt][1]));
            mx1 = fmaxf(mx1, fmaxf(sacc[nt][2], sacc[nt][3]));
        }
        mx0 = fmaxf(mx0, __shfl_xor_sync(0xffffffffu, mx0, 1));
        mx0 = fmaxf(mx0, __shfl_xor_sync(0xffffffffu, mx0, 2));
        mx1 = fmaxf(mx1, __shfl_xor_sync(0xffffffffu, mx1, 1));
        mx1 = fmaxf(mx1, __shfl_xor_sync(0xffffffffu, mx1, 2));
        float mnew0 = fmaxf(m0, mx0), mnew1 = fmaxf(m1, mx1);
        float a0 = exp2f(m0 - mnew0), a1 = exp2f(m1 - mnew1);
        m0 = mnew0; m1 = mnew1;

        float rs0 = 0.0f, rs1 = 0.0f;
        #pragma unroll
        for (int nt = 0; nt < 16; nt++) {
            float p0 = exp2f(sacc[nt][0] - mnew0);
            float p1 = exp2f(sacc[nt][1] - mnew0);
            float p2 = exp2f(sacc[nt][2] - mnew1);
            float p3 = exp2f(sacc[nt][3] - mnew1);
            sacc[nt][0] = p0; sacc[nt][1] = p1;
            sacc[nt][2] = p2; sacc[nt][3] = p3;
            rs0 += p0 + p1; rs1 += p2 + p3;
        }
        rs0 += __shfl_xor_sync(0xffffffffu, rs0, 1);
        rs0 += __shfl_xor_sync(0xffffffffu, rs0, 2);
        rs1 += __shfl_xor_sync(0xffffffffu, rs1, 1);
        rs1 += __shfl_xor_sync(0xffffffffu, rs1, 2);
        l0 = l0 * a0 + rs0;
        l1 = l1 * a1 + rs1;
        #pragma unroll
        for (int nt = 0; nt < 8; nt++) {
            oacc[nt][0] *= a0; oacc[nt][1] *= a0;
            oacc[nt][2] *= a1; oacc[nt][3] *= a1;
        }

        // ---- O += (Ph+Pl) @ (Vh+Vl) over 128 kv rows (8 pj chunks) ----
        #pragma unroll
        for (int pj = 0; pj < 8; pj++) {
            const float* se = sacc[2 * pj];
            const float* so = sacc[2 * pj + 1];
            uint32_t ph[4], pl[4];
            pack_split(se[0], se[1], ph[0], pl[0]);
            pack_split(se[2], se[3], ph[1], pl[1]);
            pack_split(so[0], so[1], ph[2], pl[2]);
            pack_split(so[2], so[3], ph[3], pl[3]);

            uint32_t vf[2][8][2];
            #pragma unroll
            for (int term = 0; term < 2; term++) {
                const uint32_t vb = stg + 32768 + term * 16384;
                #pragma unroll
                for (int np = 0; np < 4; np++) {
                    int kvrow = pj * 16 + (lane & 15);
                    int dby   = np * 32 + ((lane >> 4) * 16);
                    uint32_t t4[4];
                    ldsm_x4_t(t4, vb + sw128((uint32_t)(kvrow * 128 + dby)));
                    vf[term][np * 2][0]     = t4[0];
                    vf[term][np * 2][1]     = t4[1];
                    vf[term][np * 2 + 1][0] = t4[2];
                    vf[term][np * 2 + 1][1] = t4[3];
                }
            }
            #pragma unroll
            for (int nt = 0; nt < 8; nt++) {
                mma_bf16(oacc[nt], ph, vf[0][nt]);
                mma_bf16(oacc[nt], ph, vf[1][nt]);
                mma_bf16(oacc[nt], pl, vf[0][nt]);
            }
        }

        __syncthreads();
        if (kt + 2 < NT) { load_kv(kt & 1, kt + 2); CP_COMMIT(); }
        else CP_COMMIT();
    }

    // ---- epilogue: normalize + split-write T ----
    const float inv0 = 1.0f / l0, inv1 = 1.0f / l1;
    const size_t rb0 = (size_t)(bofs + rowg) * DM + h * 64;
    const size_t rb1 = rb0 + (size_t)8 * DM;
    #pragma unroll
    for (int nt = 0; nt < 8; nt++) {
        int col = nt * 8 + t * 2;
        split_store_pair(oacc[nt][0] * inv0, oacc[nt][1] * inv0,
                         th + rb0 + col, tl + rb0 + col);
        split_store_pair(oacc[nt][2] * inv1, oacc[nt][3] * inv1,
                         th + rb1 + col, tl + rb1 + col);
    }
}

// ---------------------------------------------------------------------------
// Launcher
// ---------------------------------------------------------------------------
extern "C" void kernel_launch(void* const* d_in, const int* in_sizes, int n_in,
                              void* d_out, int out_size)
{
    const float* x   = (const float*)d_in[0];
    const float* W_q = (const float*)d_in[1];
    const float* W_k = (const float*)d_in[2];
    const float* W_v = (const float*)d_in[3];
    const float* W_o = (const float*)d_in[4];
    float* out = (float*)d_out;

    __nv_bfloat16 *xh, *xl, *Wh, *Wl, *qkvh, *qkvl, *th, *tl;
    cudaGetSymbolAddress((void**)&xh, g_xh);
    cudaGetSymbolAddress((void**)&xl, g_xl);
    cudaGetSymbolAddress((void**)&Wh, g_Wh);
    cudaGetSymbolAddress((void**)&Wl, g_Wl);
    cudaGetSymbolAddress((void**)&qkvh, g_qkvh);
    cudaGetSymbolAddress((void**)&qkvl, g_qkvl);
    cudaGetSymbolAddress((void**)&th, g_th);
    cudaGetSymbolAddress((void**)&tl, g_tl);

    cudaFuncSetAttribute(gemm_mma_split_kernel<true>,
                         cudaFuncAttributeMaxDynamicSharedMemorySize, GEMM_SMEM);
    cudaFuncSetAttribute(gemm_mma_split_kernel<false>,
                         cudaFuncAttributeMaxDynamicSharedMemorySize, GEMM_SMEM);
    cudaFuncSetAttribute(flash_attn_mma_kernel,
                         cudaFuncAttributeMaxDynamicSharedMemorySize, ATTN_SMEM);

    const int nx4 = (int)(NX / 4), nw4 = (int)(NW / 4);
    split_bf16_kernel<<<(nx4 + 255) / 256, 256>>>(x, xh, xl, nx4);
    split_bf16_kernel<<<(nw4 + 255) / 256, 256>>>(W_q, Wh + 0 * NW, Wl + 0 * NW, nw4);
    split_bf16_kernel<<<(nw4 + 255) / 256, 256>>>(W_k, Wh + 1 * NW, Wl + 1 * NW, nw4);
    split_bf16_kernel<<<(nw4 + 255) / 256, 256>>>(W_v, Wh + 2 * NW, Wl + 2 * NW, nw4);
    split_bf16_kernel<<<(nw4 + 255) / 256, 256>>>(W_o, Wh + 3 * NW, Wl + 3 * NW, nw4);

    dim3 qkv_grid(3 * DM / 128, ROWS / 128);   // (24, 64)
    gemm_mma_split_kernel<true><<<qkv_grid, 256, GEMM_SMEM>>>(
        xh, xl, Wh, Wl, nullptr, qkvh, qkvl);

    dim3 attn_grid(SEQ / 128, BATCH * NH);     // (16, 64)
    flash_attn_mma_kernel<<<attn_grid, 256, ATTN_SMEM>>>(
        qkvh, qkvl, qkvh + NX, qkvl + NX, qkvh + 2 * NX, qkvl + 2 * NX, th, tl);

    dim3 o_grid(DM / 128, ROWS / 128);         // (8, 64)
    gemm_mma_split_kernel<false><<<o_grid, 256, GEMM_SMEM>>>(
        th, tl, Wh + 3 * NW, Wl + 3 * NW, out, nullptr, nullptr);
}

// round 7
// speedup vs baseline: 3.8106x; 1.0159x over previous
#include <cuda_runtime.h>
#include <cuda_bf16.h>
#include <cstdint>

// Problem constants
static constexpr int BATCH = 4;
static constexpr int SEQ   = 2048;
static constexpr int DM    = 1024;
static constexpr int NH    = 16;
static constexpr int DH    = 64;
static constexpr int ROWS  = BATCH * SEQ;        // 8192
static constexpr size_t NX = (size_t)ROWS * DM;  // 8388608
static constexpr size_t NW = (size_t)DM * DM;    // 1048576

// Scratch (device globals: allocation-free)
__device__ __nv_bfloat16 g_xh[NX];
__device__ __nv_bfloat16 g_xl[NX];
__device__ __nv_bfloat16 g_Wh[4 * NW];   // Wq|Wk|Wv|Wo
__device__ __nv_bfloat16 g_Wl[4 * NW];
__device__ __nv_bfloat16 g_qkvh[3 * NX]; // Q|K|V hi
__device__ __nv_bfloat16 g_qkvl[3 * NX]; // Q|K|V lo
__device__ __nv_bfloat16 g_th[NX];
__device__ __nv_bfloat16 g_tl[NX];

// ---------------------------------------------------------------------------
// Helpers
// ---------------------------------------------------------------------------
__device__ __forceinline__ uint32_t smem_u32(const void* p) {
    uint32_t a;
    asm("{ .reg .u64 t; cvta.to.shared.u64 t, %1; cvt.u32.u64 %0, t; }"
        : "=r"(a) : "l"(p));
    return a;
}
__device__ __forceinline__ uint32_t sw128(uint32_t off) {
    return off ^ ((off >> 3) & 0x70);
}
__device__ __forceinline__ void cp_async16(uint32_t saddr, const void* gaddr) {
    asm volatile("cp.async.cg.shared.global [%0], [%1], 16;"
                 :: "r"(saddr), "l"(gaddr));
}
#define CP_COMMIT() asm volatile("cp.async.commit_group;")
#define CP_WAIT(n)  asm volatile("cp.async.wait_group %0;" :: "n"(n))

__device__ __forceinline__ void ldsm_x4(uint32_t (&r)[4], uint32_t addr) {
    asm volatile("ldmatrix.sync.aligned.m8n8.x4.shared.b16 {%0,%1,%2,%3}, [%4];"
                 : "=r"(r[0]), "=r"(r[1]), "=r"(r[2]), "=r"(r[3]) : "r"(addr));
}
__device__ __forceinline__ void ldsm_x4_t(uint32_t (&r)[4], uint32_t addr) {
    asm volatile("ldmatrix.sync.aligned.m8n8.x4.trans.shared.b16 {%0,%1,%2,%3}, [%4];"
                 : "=r"(r[0]), "=r"(r[1]), "=r"(r[2]), "=r"(r[3]) : "r"(addr));
}
__device__ __forceinline__ void mma_bf16(float (&d)[4], const uint32_t (&a)[4],
                                         const uint32_t* b) {
    asm volatile(
        "mma.sync.aligned.m16n8k16.row.col.f32.bf16.bf16.f32 "
        "{%0,%1,%2,%3}, {%4,%5,%6,%7}, {%8,%9}, {%0,%1,%2,%3};"
        : "+f"(d[0]), "+f"(d[1]), "+f"(d[2]), "+f"(d[3])
        : "r"(a[0]), "r"(a[1]), "r"(a[2]), "r"(a[3]), "r"(b[0]), "r"(b[1]));
}

__device__ __forceinline__ void split_store_pair(float a, float b,
                                                 __nv_bfloat16* hp, __nv_bfloat16* lp) {
    __nv_bfloat162 h2 = __float22bfloat162_rn(make_float2(a, b));
    float2 hf = __bfloat1622float2(h2);
    __nv_bfloat162 l2 = __float22bfloat162_rn(make_float2(a - hf.x, b - hf.y));
    *reinterpret_cast<uint32_t*>(hp) = *reinterpret_cast<const uint32_t*>(&h2);
    *reinterpret_cast<uint32_t*>(lp) = *reinterpret_cast<const uint32_t*>(&l2);
}
__device__ __forceinline__ void pack_split(float a, float b, uint32_t& ph, uint32_t& pl) {
    __nv_bfloat162 h2 = __float22bfloat162_rn(make_float2(a, b));
    float2 hf = __bfloat1622float2(h2);
    __nv_bfloat162 l2 = __float22bfloat162_rn(make_float2(a - hf.x, b - hf.y));
    ph = *reinterpret_cast<const uint32_t*>(&h2);
    pl = *reinterpret_cast<const uint32_t*>(&l2);
}

// ---------------------------------------------------------------------------
// fp32 -> (hi, lo) bf16 split
// ---------------------------------------------------------------------------
__global__ __launch_bounds__(256) void split_bf16_kernel(
    const float* __restrict__ src, __nv_bfloat16* __restrict__ hi,
    __nv_bfloat16* __restrict__ lo, int n4)
{
    int i = blockIdx.x * blockDim.x + threadIdx.x;
    if (i >= n4) return;
    float4 v = reinterpret_cast<const float4*>(src)[i];
    __nv_bfloat162 h0 = __float22bfloat162_rn(make_float2(v.x, v.y));
    __nv_bfloat162 h1 = __float22bfloat162_rn(make_float2(v.z, v.w));
    float2 f0 = __bfloat1622float2(h0), f1 = __bfloat1622float2(h1);
    __nv_bfloat162 l0 = __float22bfloat162_rn(make_float2(v.x - f0.x, v.y - f0.y));
    __nv_bfloat162 l1 = __float22bfloat162_rn(make_float2(v.z - f1.x, v.w - f1.y));
    uint2 hv, lv;
    hv.x = *reinterpret_cast<uint32_t*>(&h0); hv.y = *reinterpret_cast<uint32_t*>(&h1);
    lv.x = *reinterpret_cast<uint32_t*>(&l0); lv.y = *reinterpret_cast<uint32_t*>(&l1);
    reinterpret_cast<uint2*>(hi)[i] = hv;
    reinterpret_cast<uint2*>(lo)[i] = lv;
}

// ---------------------------------------------------------------------------
// bf16-split GEMM (NT), K = 1024 fixed (unchanged — proven)
// ---------------------------------------------------------------------------
static constexpr int TILE_B    = 128 * 128;
static constexpr int STAGE_B   = 2 * TILE_B;
static constexpr int GSTAGES   = 4;
static constexpr int GEMM_SMEM = GSTAGES * STAGE_B;   // 131072

template <bool SPLIT_OUT>
__global__ __launch_bounds__(256, 1) void gemm_mma_split_kernel(
    const __nv_bfloat16* __restrict__ Ah, const __nv_bfloat16* __restrict__ Al,
    const __nv_bfloat16* __restrict__ Bh, const __nv_bfloat16* __restrict__ Bl,
    float* __restrict__ C, __nv_bfloat16* __restrict__ Ch,
    __nv_bfloat16* __restrict__ Cl)
{
    extern __shared__ char smem[];
    const uint32_t sbase = smem_u32(smem);
    constexpr int K   = DM;
    constexpr int NKT = K / 32;

    const int tid   = threadIdx.x;
    const int wid   = tid >> 5;
    const int lane  = tid & 31;
    const int warpm = wid >> 2;
    const int warpn = wid & 3;
    const int row0  = blockIdx.y * 128;
    const int col0  = blockIdx.x * 128;

    auto load_stage = [&](int s, int kt) {
        const uint32_t As = sbase + s * STAGE_B;
        const uint32_t Bs = As + TILE_B;
        const size_t kofs = (size_t)kt * 32;
        const __nv_bfloat16* Ah0 = Ah + (size_t)row0 * K + kofs;
        const __nv_bfloat16* Al0 = Al + (size_t)row0 * K + kofs;
        const __nv_bfloat16* Bh0 = Bh + (size_t)col0 * K + kofs;
        const __nv_bfloat16* Bl0 = Bl + (size_t)col0 * K + kofs;
        #pragma unroll
        for (int t = 0; t < 4; t++) {
            int v = t * 256 + tid;
            int r = v >> 3;
            int c = v & 7;
            uint32_t soff = sw128((uint32_t)(r * 128 + c * 16));
            cp_async16(As + soff, (c < 4 ? Ah0 : Al0) + (size_t)r * K + (c & 3) * 8);
            cp_async16(Bs + soff, (c < 4 ? Bh0 : Bl0) + (size_t)r * K + (c & 3) * 8);
        }
    };

    float acc[4][4][4];
    #pragma unroll
    for (int i = 0; i < 4; i++)
        #pragma unroll
        for (int j = 0; j < 4; j++)
            #pragma unroll
            for (int k = 0; k < 4; k++) acc[i][j][k] = 0.0f;

    load_stage(0, 0); CP_COMMIT();
    load_stage(1, 1); CP_COMMIT();
    load_stage(2, 2); CP_COMMIT();

    for (int kt = 0; kt < NKT; kt++) {
        CP_WAIT(2);
        __syncthreads();

        const uint32_t As = sbase + (kt & 3) * STAGE_B;
        const uint32_t Bs = As + TILE_B;

        #pragma unroll
        for (int kc = 0; kc < 2; kc++) {
            const int jh = kc * 2;
            const int jl = 4 + kc * 2;

            uint32_t Ahf[4][4], Bhf[4][2];
            #pragma unroll
            for (int mt = 0; mt < 4; mt++) {
                int row = warpm * 64 + mt * 16 + (lane & 15);
                ldsm_x4(Ahf[mt], As + sw128((uint32_t)(row * 128 + (jh + (lane >> 4)) * 16)));
            }
            #pragma unroll
            for (int p = 0; p < 2; p++) {
                int row = warpn * 32 + p * 16 + ((lane >> 4) << 3) + (lane & 7);
                uint32_t t4[4];
                ldsm_x4(t4, Bs + sw128((uint32_t)(row * 128 + (jh + ((lane >> 3) & 1)) * 16)));
                Bhf[p * 2][0]     = t4[0]; Bhf[p * 2][1]     = t4[1];
                Bhf[p * 2 + 1][0] = t4[2]; Bhf[p * 2 + 1][1] = t4[3];
            }
            #pragma unroll
            for (int mt = 0; mt < 4; mt++)
                #pragma unroll
                for (int nt = 0; nt < 4; nt++)
                    mma_bf16(acc[mt][nt], Ahf[mt], Bhf[nt]);

            uint32_t Blf[4][2];
            #pragma unroll
            for (int p = 0; p < 2; p++) {
                int row = warpn * 32 + p * 16 + ((lane >> 4) << 3) + (lane & 7);
                uint32_t t4[4];
                ldsm_x4(t4, Bs + sw128((uint32_t)(row * 128 + (jl + ((lane >> 3) & 1)) * 16)));
                Blf[p * 2][0]     = t4[0]; Blf[p * 2][1]     = t4[1];
                Blf[p * 2 + 1][0] = t4[2]; Blf[p * 2 + 1][1] = t4[3];
            }
            #pragma unroll
            for (int mt = 0; mt < 4; mt++)
                #pragma unroll
                for (int nt = 0; nt < 4; nt++)
                    mma_bf16(acc[mt][nt], Ahf[mt], Blf[nt]);

            uint32_t Alf[4][4];
            #pragma unroll
            for (int mt = 0; mt < 4; mt++) {
                int row = warpm * 64 + mt * 16 + (lane & 15);
                ldsm_x4(Alf[mt], As + sw128((uint32_t)(row * 128 + (jl + (lane >> 4)) * 16)));
            }
            #pragma unroll
            for (int mt = 0; mt < 4; mt++)
                #pragma unroll
                for (int nt = 0; nt < 4; nt++)
                    mma_bf16(acc[mt][nt], Alf[mt], Bhf[nt]);
        }

        if (kt + 3 < NKT) load_stage((kt + 3) & 3, kt + 3);
        CP_COMMIT();
    }

    const int g = lane >> 2;
    const int t = lane & 3;
    if (SPLIT_OUT) {
        const int mat  = col0 >> 10;
        const int colb = col0 & 1023;
        __nv_bfloat16* ch = Ch + (size_t)mat * NX;
        __nv_bfloat16* cl = Cl + (size_t)mat * NX;
        #pragma unroll
        for (int mt = 0; mt < 4; mt++)
            #pragma unroll
            for (int nt = 0; nt < 4; nt++) {
                int row = row0 + warpm * 64 + mt * 16 + g;
                int col = colb + warpn * 32 + nt * 8 + t * 2;
                split_store_pair(acc[mt][nt][0], acc[mt][nt][1],
                                 ch + (size_t)row * DM + col, cl + (size_t)row * DM + col);
                split_store_pair(acc[mt][nt][2], acc[mt][nt][3],
                                 ch + (size_t)(row + 8) * DM + col,
                                 cl + (size_t)(row + 8) * DM + col);
            }
    } else {
        #pragma unroll
        for (int mt = 0; mt < 4; mt++)
            #pragma unroll
            for (int nt = 0; nt < 4; nt++) {
                int row = row0 + warpm * 64 + mt * 16 + g;
                int col = col0 + warpn * 32 + nt * 8 + t * 2;
                float2 v0 = make_float2(acc[mt][nt][0], acc[mt][nt][1]);
                float2 v1 = make_float2(acc[mt][nt][2], acc[mt][nt][3]);
                *reinterpret_cast<float2*>(&C[(size_t)row * DM + col])       = v0;
                *reinterpret_cast<float2*>(&C[(size_t)(row + 8) * DM + col]) = v1;
            }
    }
}

// ---------------------------------------------------------------------------
// Tensor-core flash attention (split-bf16, causal), BM=64, BN=64.
// One CTA = 64 query rows of one (b,h); 4 warps x 16 rows; 128 threads.
// SMEM = Q 16KB + 2 stages x 32KB = 80KB  ->  2 CTAs/SM for phase overlap.
// log2-domain softmax. Mask only on the diagonal (last) tile.
// ---------------------------------------------------------------------------
static constexpr int ATTN_SMEM = 16384 + 2 * 32768;   // 81920
static constexpr float SCALE_L2E = 0.125f * 1.4426950408889634f;

__global__ __launch_bounds__(128) void flash_attn_mma_kernel(
    const __nv_bfloat16* __restrict__ qh, const __nv_bfloat16* __restrict__ ql,
    const __nv_bfloat16* __restrict__ kh, const __nv_bfloat16* __restrict__ kl,
    const __nv_bfloat16* __restrict__ vh, const __nv_bfloat16* __restrict__ vl,
    __nv_bfloat16* __restrict__ th, __nv_bfloat16* __restrict__ tl)
{
    extern __shared__ char smem[];
    const uint32_t sbase = smem_u32(smem);

    const int tid  = threadIdx.x;
    const int wid  = tid >> 5;        // 0..3
    const int lane = tid & 31;
    const int g    = lane >> 2;
    const int t    = lane & 3;

    const int qb = (SEQ / 64 - 1) - blockIdx.x;    // heavy blocks first (0..31)
    const int bh = blockIdx.y;
    const int b  = bh >> 4;
    const int h  = bh & 15;
    const int q0 = qb * 64;
    const int bofs = b * SEQ;
    const int NT = qb + 1;                          // kv tiles of 64
    const int rowg = q0 + wid * 16 + g;

    auto load_q = [&]() {
        #pragma unroll
        for (int term = 0; term < 2; term++) {
            const __nv_bfloat16* src = term ? ql : qh;
            #pragma unroll
            for (int tt = 0; tt < 4; tt++) {
                int v = tt * 128 + tid;     // 0..511 -> 64 rows x 8 chunks
                int r = v >> 3;
                int c = v & 7;
                cp_async16(sbase + term * 8192 + sw128((uint32_t)(r * 128 + c * 16)),
                           src + (size_t)(bofs + q0 + r) * DM + h * 64 + c * 8);
            }
        }
    };
    auto load_kv = [&](int stage, int kt2) {
        const int kv = kt2 * 64;
        const uint32_t base = sbase + 16384 + stage * 32768;
        const __nv_bfloat16* bufs[4] = {kh, kl, vh, vl};
        #pragma unroll
        for (int buf = 0; buf < 4; buf++) {
            #pragma unroll
            for (int tt = 0; tt < 4; tt++) {
                int v = tt * 128 + tid;
                int r = v >> 3;             // 0..63
                int c = v & 7;
                cp_async16(base + buf * 8192 + sw128((uint32_t)(r * 128 + c * 16)),
                           bufs[buf] + (size_t)(bofs + kv + r) * DM + h * 64 + c * 8);
            }
        }
    };

    load_q();
    load_kv(0, 0); CP_COMMIT();
    load_kv(1, NT > 1 ? 1 : 0); CP_COMMIT();
    CP_WAIT(1);
    __syncthreads();

    // Q fragments persistent: [term][j][4]
    uint32_t qf[2][4][4];
    #pragma unroll
    for (int term = 0; term < 2; term++) {
        const uint32_t qbse = sbase + term * 8192;
        #pragma unroll
        for (int j = 0; j < 4; j++) {
            int row   = wid * 16 + (lane & 15);
            int chunk = j * 2 + (lane >> 4);
            ldsm_x4(qf[term][j], qbse + sw128((uint32_t)(row * 128 + chunk * 16)));
        }
    }

    float m0 = -1e30f, m1 = -1e30f, l0 = 0.0f, l1 = 0.0f;
    float oacc[8][4];
    #pragma unroll
    for (int nt = 0; nt < 8; nt++)
        #pragma unroll
        for (int c = 0; c < 4; c++) oacc[nt][c] = 0.0f;

    for (int kt = 0; kt < NT; kt++) {
        if (kt + 1 < NT) { CP_WAIT(1); } else { CP_WAIT(0); }
        __syncthreads();

        const int kv0 = kt * 64;
        const uint32_t stg = sbase + 16384 + (kt & 1) * 32768;

        // ---- S = (Qh+Ql) @ (Kh+Kl)^T ----
        float sacc[8][4];
        #pragma unroll
        for (int nt = 0; nt < 8; nt++)
            #pragma unroll
            for (int c = 0; c < 4; c++) sacc[nt][c] = 0.0f;

        #pragma unroll
        for (int j = 0; j < 4; j++) {
            uint32_t kf[2][8][2];
            #pragma unroll
            for (int term = 0; term < 2; term++) {
                const uint32_t kb = stg + term * 8192;
                #pragma unroll
                for (int np = 0; np < 4; np++) {
                    int row   = np * 16 + ((lane >> 4) << 3) + (lane & 7);
                    int chunk = j * 2 + ((lane >> 3) & 1);
                    uint32_t t4[4];
                    ldsm_x4(t4, kb + sw128((uint32_t)(row * 128 + chunk * 16)));
                    kf[term][np * 2][0]     = t4[0];
                    kf[term][np * 2][1]     = t4[1];
                    kf[term][np * 2 + 1][0] = t4[2];
                    kf[term][np * 2 + 1][1] = t4[3];
                }
            }
            #pragma unroll
            for (int nt = 0; nt < 8; nt++) {
                mma_bf16(sacc[nt], qf[0][j], kf[0][nt]);
                mma_bf16(sacc[nt], qf[0][j], kf[1][nt]);
                mma_bf16(sacc[nt], qf[1][j], kf[0][nt]);
            }
        }

        // ---- scale to log2 domain + causal mask (diagonal tile only) ----
        const bool lastt = (kt == NT - 1);
        #pragma unroll
        for (int nt = 0; nt < 8; nt++) {
            #pragma unroll
            for (int c = 0; c < 4; c++) {
                float s = sacc[nt][c] * SCALE_L2E;
                if (lastt) {
                    int col = kv0 + nt * 8 + t * 2 + (c & 1);
                    int row = (c < 2) ? rowg : rowg + 8;
                    if (col > row) s = -1e30f;
                }
                sacc[nt][c] = s;
            }
        }

        // ---- online softmax (base-2) ----
        float mx0 = -1e30f, mx1 = -1e30f;
        #pragma unroll
        for (int nt = 0; nt < 8; nt++) {
            mx0 = fmaxf(mx0, fmaxf(sacc[nt][0], sacc[nt][1]));
            mx1 = fmaxf(mx1, fmaxf(sacc[nt][2], sacc[nt][3]));
        }
        mx0 = fmaxf(mx0, __shfl_xor_sync(0xffffffffu, mx0, 1));
        mx0 = fmaxf(mx0, __shfl_xor_sync(0xffffffffu, mx0, 2));
        mx1 = fmaxf(mx1, __shfl_xor_sync(0xffffffffu, mx1, 1));
        mx1 = fmaxf(mx1, __shfl_xor_sync(0xffffffffu, mx1, 2));
        float mnew0 = fmaxf(m0, mx0), mnew1 = fmaxf(m1, mx1);
        float a0 = exp2f(m0 - mnew0), a1 = exp2f(m1 - mnew1);
        m0 = mnew0; m1 = mnew1;

        float rs0 = 0.0f, rs1 = 0.0f;
        #pragma unroll
        for (int nt = 0; nt < 8; nt++) {
            float p0 = exp2f(sacc[nt][0] - mnew0);
            float p1 = exp2f(sacc[nt][1] - mnew0);
            float p2 = exp2f(sacc[nt][2] - mnew1);
            float p3 = exp2f(sacc[nt][3] - mnew1);
            sacc[nt][0] = p0; sacc[nt][1] = p1;
            sacc[nt][2] = p2; sacc[nt][3] = p3;
            rs0 += p0 + p1; rs1 += p2 + p3;
        }
        rs0 += __shfl_xor_sync(0xffffffffu, rs0, 1);
        rs0 += __shfl_xor_sync(0xffffffffu, rs0, 2);
        rs1 += __shfl_xor_sync(0xffffffffu, rs1, 1);
        rs1 += __shfl_xor_sync(0xffffffffu, rs1, 2);
        l0 = l0 * a0 + rs0;
        l1 = l1 * a1 + rs1;
        #pragma unroll
        for (int nt = 0; nt < 8; nt++) {
            oacc[nt][0] *= a0; oacc[nt][1] *= a0;
            oacc[nt][2] *= a1; oacc[nt][3] *= a1;
        }

        // ---- O += (Ph+Pl) @ (Vh+Vl) ----
        #pragma unroll
        for (int pj = 0; pj < 4; pj++) {
            const float* se = sacc[2 * pj];
            const float* so = sacc[2 * pj + 1];
            uint32_t ph[4], pl[4];
            pack_split(se[0], se[1], ph[0], pl[0]);
            pack_split(se[2], se[3], ph[1], pl[1]);
            pack_split(so[0], so[1], ph[2], pl[2]);
            pack_split(so[2], so[3], ph[3], pl[3]);

            uint32_t vf[2][8][2];
            #pragma unroll
            for (int term = 0; term < 2; term++) {
                const uint32_t vb = stg + 16384 + term * 8192;
                #pragma unroll
                for (int np = 0; np < 4; np++) {
                    int kvrow = pj * 16 + (lane & 15);
                    int dby   = np * 32 + ((lane >> 4) * 16);
                    uint32_t t4[4];
                    ldsm_x4_t(t4, vb + sw128((uint32_t)(kvrow * 128 + dby)));
                    vf[term][np * 2][0]     = t4[0];
                    vf[term][np * 2][1]     = t4[1];
                    vf[term][np * 2 + 1][0] = t4[2];
                    vf[term][np * 2 + 1][1] = t4[3];
                }
            }
            #pragma unroll
            for (int nt = 0; nt < 8; nt++) {
                mma_bf16(oacc[nt], ph, vf[0][nt]);
                mma_bf16(oacc[nt], ph, vf[1][nt]);
                mma_bf16(oacc[nt], pl, vf[0][nt]);
            }
        }

        __syncthreads();
        if (kt + 2 < NT) { load_kv(kt & 1, kt + 2); CP_COMMIT(); }
        else CP_COMMIT();
    }

    // ---- epilogue: normalize + split-write T ----
    const float inv0 = 1.0f / l0, inv1 = 1.0f / l1;
    const size_t rb0 = (size_t)(bofs + rowg) * DM + h * 64;
    const size_t rb1 = rb0 + (size_t)8 * DM;
    #pragma unroll
    for (int nt = 0; nt < 8; nt++) {
        int col = nt * 8 + t * 2;
        split_store_pair(oacc[nt][0] * inv0, oacc[nt][1] * inv0,
                         th + rb0 + col, tl + rb0 + col);
        split_store_pair(oacc[nt][2] * inv1, oacc[nt][3] * inv1,
                         th + rb1 + col, tl + rb1 + col);
    }
}

// ---------------------------------------------------------------------------
// Launcher
// ---------------------------------------------------------------------------
extern "C" void kernel_launch(void* const* d_in, const int* in_sizes, int n_in,
                              void* d_out, int out_size)
{
    const float* x   = (const float*)d_in[0];
    const float* W_q = (const float*)d_in[1];
    const float* W_k = (const float*)d_in[2];
    const float* W_v = (const float*)d_in[3];
    const float* W_o = (const float*)d_in[4];
    float* out = (float*)d_out;

    __nv_bfloat16 *xh, *xl, *Wh, *Wl, *qkvh, *qkvl, *th, *tl;
    cudaGetSymbolAddress((void**)&xh, g_xh);
    cudaGetSymbolAddress((void**)&xl, g_xl);
    cudaGetSymbolAddress((void**)&Wh, g_Wh);
    cudaGetSymbolAddress((void**)&Wl, g_Wl);
    cudaGetSymbolAddress((void**)&qkvh, g_qkvh);
    cudaGetSymbolAddress((void**)&qkvl, g_qkvl);
    cudaGetSymbolAddress((void**)&th, g_th);
    cudaGetSymbolAddress((void**)&tl, g_tl);

    cudaFuncSetAttribute(gemm_mma_split_kernel<true>,
                         cudaFuncAttributeMaxDynamicSharedMemorySize, GEMM_SMEM);
    cudaFuncSetAttribute(gemm_mma_split_kernel<false>,
                         cudaFuncAttributeMaxDynamicSharedMemorySize, GEMM_SMEM);
    cudaFuncSetAttribute(flash_attn_mma_kernel,
                         cudaFuncAttributeMaxDynamicSharedMemorySize, ATTN_SMEM);

    const int nx4 = (int)(NX / 4), nw4 = (int)(NW / 4);
    split_bf16_kernel<<<(nx4 + 255) / 256, 256>>>(x, xh, xl, nx4);
    split_bf16_kernel<<<(nw4 + 255) / 256, 256>>>(W_q, Wh + 0 * NW, Wl + 0 * NW, nw4);
    split_bf16_kernel<<<(nw4 + 255) / 256, 256>>>(W_k, Wh + 1 * NW, Wl + 1 * NW, nw4);
    split_bf16_kernel<<<(nw4 + 255) / 256, 256>>>(W_v, Wh + 2 * NW, Wl + 2 * NW, nw4);
    split_bf16_kernel<<<(nw4 + 255) / 256, 256>>>(W_o, Wh + 3 * NW, Wl + 3 * NW, nw4);

    dim3 qkv_grid(3 * DM / 128, ROWS / 128);   // (24, 64)
    gemm_mma_split_kernel<true><<<qkv_grid, 256, GEMM_SMEM>>>(
        xh, xl, Wh, Wl, nullptr, qkvh, qkvl);

    dim3 attn_grid(SEQ / 64, BATCH * NH);      // (32, 64)
    flash_attn_mma_kernel<<<attn_grid, 128, ATTN_SMEM>>>(
        qkvh, qkvl, qkvh + NX, qkvl + NX, qkvh + 2 * NX, qkvl + 2 * NX, th, tl);

    dim3 o_grid(DM / 128, ROWS / 128);         // (8, 64)
    gemm_mma_split_kernel<false><<<o_grid, 256, GEMM_SMEM>>>(
        th, tl, Wh + 3 * NW, Wl + 3 * NW, out, nullptr, nullptr);
}